// round 4
// baseline (speedup 1.0000x reference)
#include <cuda_runtime.h>
#include <math.h>

// Problem dims
#define B_   4
#define T_   2048
#define D_   1024
#define H_   16
#define HD_  64
#define BT_  (B_*T_)          // 8192 rows

// ---------------- scratch (device globals: no runtime allocation) ----------
__device__ float g_xn[BT_*D_];   // layernorm output       [BT, D]
__device__ float g_q [BT_*D_];   // Q  [B,H,T,HD]
__device__ float g_k [BT_*D_];   // K  [B,H,T,HD]
__device__ float g_v [BT_*D_];   // V  [B,H,T,HD]
__device__ float g_ao[BT_*D_];   // attention out          [B,T,D]

// ======================= LayerNorm =========================================
__global__ void ln_kernel(const float* __restrict__ x,
                          const float* __restrict__ gamma,
                          const float* __restrict__ beta) {
    int row = blockIdx.x;
    int tid = threadIdx.x;                         // 256 threads, 4 floats each
    const float4* xr = reinterpret_cast<const float4*>(x + (size_t)row * D_);
    float4 v = xr[tid];
    float s  = v.x + v.y + v.z + v.w;
    float sq = v.x*v.x + v.y*v.y + v.z*v.z + v.w*v.w;
    #pragma unroll
    for (int o = 16; o > 0; o >>= 1) {
        s  += __shfl_xor_sync(0xffffffffu, s,  o);
        sq += __shfl_xor_sync(0xffffffffu, sq, o);
    }
    __shared__ float ss[8], sq2[8];
    __shared__ float mu_s, rs_s;
    if ((tid & 31) == 0) { ss[tid >> 5] = s; sq2[tid >> 5] = sq; }
    __syncthreads();
    if (tid == 0) {
        float a = 0.f, b2 = 0.f;
        #pragma unroll
        for (int i = 0; i < 8; i++) { a += ss[i]; b2 += sq2[i]; }
        float mu  = a * (1.0f / D_);
        float var = b2 * (1.0f / D_) - mu * mu;
        mu_s = mu;
        rs_s = rsqrtf(var + 1e-5f);
    }
    __syncthreads();
    float mu = mu_s, rs = rs_s;
    float4 g  = reinterpret_cast<const float4*>(gamma)[tid];
    float4 be = reinterpret_cast<const float4*>(beta)[tid];
    float4 o;
    o.x = (v.x - mu) * rs * g.x + be.x;
    o.y = (v.y - mu) * rs * g.y + be.y;
    o.z = (v.z - mu) * rs * g.z + be.z;
    o.w = (v.w - mu) * rs * g.w + be.w;
    reinterpret_cast<float4*>(g_xn + (size_t)row * D_)[tid] = o;
}

// ======================= QKV GEMM (128x128x8 SIMT, prefetch) ===============
// C = g_xn[8192,1024] @ w_qkv[1024,3072] + b_qkv ; scatter to q/k/v [B,H,T,HD]
__global__ __launch_bounds__(256, 2) void qkv_gemm(const float* __restrict__ Bw,
                                                   const float* __restrict__ bias) {
    const int N = 3 * D_, K = D_;
    __shared__ float As[8][132];
    __shared__ float Bs[8][132];
    int tid = threadIdx.x;
    int tx = tid & 15, ty = tid >> 4;
    int m0 = blockIdx.y * 128, n0 = blockIdx.x * 128;
    int arow = tid >> 1, ak = (tid & 1) * 4;
    int brow = tid >> 5, bc = (tid & 31) * 4;
    const float* Ag = g_xn + (size_t)(m0 + arow) * K + ak;
    const float* Bg = Bw + (size_t)brow * N + n0 + bc;

    float4 a_pre = *reinterpret_cast<const float4*>(Ag);
    float4 b_pre = *reinterpret_cast<const float4*>(Bg);
    float acc[8][8] = {};

    for (int k0 = 0; k0 < K; k0 += 8) {
        As[ak+0][arow] = a_pre.x; As[ak+1][arow] = a_pre.y;
        As[ak+2][arow] = a_pre.z; As[ak+3][arow] = a_pre.w;
        *reinterpret_cast<float4*>(&Bs[brow][bc]) = b_pre;
        __syncthreads();
        if (k0 + 8 < K) {
            a_pre = *reinterpret_cast<const float4*>(Ag + k0 + 8);
            b_pre = *reinterpret_cast<const float4*>(Bg + (size_t)(k0 + 8) * N);
        }
        #pragma unroll
        for (int kk = 0; kk < 8; kk++) {
            float ar[8], br[8];
            *reinterpret_cast<float4*>(ar)     = *reinterpret_cast<const float4*>(&As[kk][ty*8]);
            *reinterpret_cast<float4*>(ar + 4) = *reinterpret_cast<const float4*>(&As[kk][ty*8+4]);
            *reinterpret_cast<float4*>(br)     = *reinterpret_cast<const float4*>(&Bs[kk][tx*8]);
            *reinterpret_cast<float4*>(br + 4) = *reinterpret_cast<const float4*>(&Bs[kk][tx*8+4]);
            #pragma unroll
            for (int i = 0; i < 8; i++)
                #pragma unroll
                for (int j = 0; j < 8; j++)
                    acc[i][j] = fmaf(ar[i], br[j], acc[i][j]);
        }
        __syncthreads();
    }

    int btrow = m0 + ty * 8;
    int cbase = n0 + tx * 8;
    #pragma unroll
    for (int i = 0; i < 8; i++) {
        int bt = btrow + i;
        int b  = bt >> 11;            // /2048
        int t  = bt & 2047;
        #pragma unroll
        for (int j = 0; j < 8; j++) {
            int c   = cbase + j;
            float val = acc[i][j] + bias[c];
            int s   = c >> 10;        // 0=q,1=k,2=v
            int rem = c & 1023;
            int h   = rem >> 6;
            int d   = rem & 63;
            float* dst = (s == 0) ? g_q : ((s == 1) ? g_k : g_v);
            dst[((size_t)((b * H_ + h) * T_) + t) * HD_ + d] = val;
        }
    }
}

// ======================= Flash Attention (SIMT) ============================
// Per block: one (b, h, 128-row q tile). 256 threads.
// smem: Qt[64][132] (Q transposed), Kt[64][132], Vs[128][68], Ss[128][132],
//       alpha[128], linv[128]  -> 171008 bytes dynamic.
#define ATTN_SMEM 171008

__global__ __launch_bounds__(256, 1) void attn_kernel() {
    extern __shared__ float sm[];
    float* Qt      = sm;                     // 64*132
    float* Kt      = Qt + 64 * 132;          // 64*132
    float* Vs      = Kt + 64 * 132;          // 128*68
    float* Ss      = Vs + 128 * 68;          // 128*132
    float* alpha_s = Ss + 128 * 132;         // 128
    float* linv_s  = alpha_s + 128;          // 128

    int tid = threadIdx.x;
    int tx = tid & 15, ty = tid >> 4;
    int qtile = blockIdx.x, h = blockIdx.y, b = blockIdx.z;
    size_t bh = (size_t)(b * H_ + h) * T_ * HD_;
    const float* Qg = g_q + bh + (size_t)qtile * 128 * HD_;

    // Load Q tile transposed: Qt[d][row]
    for (int i = tid; i < 128 * 16; i += 256) {
        int row = i >> 4, c4 = (i & 15) * 4;
        float4 f = *reinterpret_cast<const float4*>(Qg + row * HD_ + c4);
        Qt[(c4+0)*132 + row] = f.x;
        Qt[(c4+1)*132 + row] = f.y;
        Qt[(c4+2)*132 + row] = f.z;
        Qt[(c4+3)*132 + row] = f.w;
    }

    float O[8][4] = {};              // rows ty*8+i, cols tx*4+j
    float m_run = -1e30f, l_run = 0.f;
    int srow = tid >> 1, shalf = tid & 1;

    for (int kt = 0; kt < 16; kt++) {
        __syncthreads();             // Kt/Vs (and Qt first iter) safe to (over)write
        const float* Kg = g_k + bh + (size_t)kt * 128 * HD_;
        const float* Vg = g_v + bh + (size_t)kt * 128 * HD_;
        for (int i = tid; i < 128 * 16; i += 256) {
            int row = i >> 4, c4 = (i & 15) * 4;
            float4 f = *reinterpret_cast<const float4*>(Kg + row * HD_ + c4);
            Kt[(c4+0)*132 + row] = f.x;
            Kt[(c4+1)*132 + row] = f.y;
            Kt[(c4+2)*132 + row] = f.z;
            Kt[(c4+3)*132 + row] = f.w;
            float4 g2 = *reinterpret_cast<const float4*>(Vg + row * HD_ + c4);
            *reinterpret_cast<float4*>(&Vs[row * 68 + c4]) = g2;
        }
        __syncthreads();

        // ---- S = Q K^T (128x128, k=64), 8x8 micro-tile -------------------
        float sacc[8][8] = {};
        #pragma unroll 4
        for (int kk = 0; kk < 64; kk++) {
            float ar[8], br[8];
            *reinterpret_cast<float4*>(ar)     = *reinterpret_cast<const float4*>(&Qt[kk*132 + ty*8]);
            *reinterpret_cast<float4*>(ar + 4) = *reinterpret_cast<const float4*>(&Qt[kk*132 + ty*8+4]);
            *reinterpret_cast<float4*>(br)     = *reinterpret_cast<const float4*>(&Kt[kk*132 + tx*8]);
            *reinterpret_cast<float4*>(br + 4) = *reinterpret_cast<const float4*>(&Kt[kk*132 + tx*8+4]);
            #pragma unroll
            for (int i = 0; i < 8; i++)
                #pragma unroll
                for (int j = 0; j < 8; j++)
                    sacc[i][j] = fmaf(ar[i], br[j], sacc[i][j]);
        }
        const float scale = 0.125f;   // HD^-0.5
        #pragma unroll
        for (int i = 0; i < 8; i++) {
            float4 s0 = make_float4(sacc[i][0]*scale, sacc[i][1]*scale,
                                    sacc[i][2]*scale, sacc[i][3]*scale);
            float4 s1 = make_float4(sacc[i][4]*scale, sacc[i][5]*scale,
                                    sacc[i][6]*scale, sacc[i][7]*scale);
            *reinterpret_cast<float4*>(&Ss[(ty*8+i)*132 + tx*8])     = s0;
            *reinterpret_cast<float4*>(&Ss[(ty*8+i)*132 + tx*8 + 4]) = s1;
        }
        __syncthreads();

        // ---- online softmax: 2 threads per row, 64 cols each --------------
        float* Srow = Ss + srow * 132 + shalf * 64;
        float mloc = -1e30f;
        #pragma unroll 4
        for (int j = 0; j < 64; j++) mloc = fmaxf(mloc, Srow[j]);
        mloc = fmaxf(mloc, __shfl_xor_sync(0xffffffffu, mloc, 1));
        float m_new = fmaxf(m_run, mloc);
        float al = __expf(m_run - m_new);
        float sl = 0.f;
        #pragma unroll 4
        for (int j = 0; j < 64; j++) {
            float p = __expf(Srow[j] - m_new);
            Srow[j] = p;
            sl += p;
        }
        sl += __shfl_xor_sync(0xffffffffu, sl, 1);
        l_run = l_run * al + sl;
        m_run = m_new;
        if (shalf == 0) alpha_s[srow] = al;
        __syncthreads();

        // ---- O = O*alpha + P V  (128x64, k=128), 8x4 micro-tile ----------
        #pragma unroll
        for (int i = 0; i < 8; i++) {
            float a2 = alpha_s[ty*8 + i];
            #pragma unroll
            for (int j = 0; j < 4; j++) O[i][j] *= a2;
        }
        #pragma unroll 4
        for (int kk = 0; kk < 128; kk++) {
            float pr[8];
            #pragma unroll
            for (int i = 0; i < 8; i++) pr[i] = Ss[(ty*8+i)*132 + kk];
            float4 vv = *reinterpret_cast<const float4*>(&Vs[kk*68 + tx*4]);
            float br4[4] = {vv.x, vv.y, vv.z, vv.w};
            #pragma unroll
            for (int i = 0; i < 8; i++)
                #pragma unroll
                for (int j = 0; j < 4; j++)
                    O[i][j] = fmaf(pr[i], br4[j], O[i][j]);
        }
    }

    if (shalf == 0) linv_s[srow] = 1.f / l_run;
    __syncthreads();

    // write to g_ao [B,T,D], d = h*64 + col
    size_t outbase = ((size_t)b * T_ + qtile * 128) * D_ + h * HD_;
    #pragma unroll
    for (int i = 0; i < 8; i++) {
        int row = ty * 8 + i;
        float li = linv_s[row];
        float4 o4 = make_float4(O[i][0]*li, O[i][1]*li, O[i][2]*li, O[i][3]*li);
        *reinterpret_cast<float4*>(&g_ao[outbase + (size_t)row * D_ + tx*4]) = o4;
    }
}

// ======================= Proj GEMM + bias + residual =======================
__global__ __launch_bounds__(256, 2) void proj_gemm(const float* __restrict__ Bw,
                                                    const float* __restrict__ bias,
                                                    const float* __restrict__ xres,
                                                    float* __restrict__ out) {
    const int N = D_, K = D_;
    __shared__ float As[8][132];
    __shared__ float Bs[8][132];
    int tid = threadIdx.x;
    int tx = tid & 15, ty = tid >> 4;
    int m0 = blockIdx.y * 128, n0 = blockIdx.x * 128;
    int arow = tid >> 1, ak = (tid & 1) * 4;
    int brow = tid >> 5, bc = (tid & 31) * 4;
    const float* Ag = g_ao + (size_t)(m0 + arow) * K + ak;
    const float* Bg = Bw + (size_t)brow * N + n0 + bc;

    float4 a_pre = *reinterpret_cast<const float4*>(Ag);
    float4 b_pre = *reinterpret_cast<const float4*>(Bg);
    float acc[8][8] = {};

    for (int k0 = 0; k0 < K; k0 += 8) {
        As[ak+0][arow] = a_pre.x; As[ak+1][arow] = a_pre.y;
        As[ak+2][arow] = a_pre.z; As[ak+3][arow] = a_pre.w;
        *reinterpret_cast<float4*>(&Bs[brow][bc]) = b_pre;
        __syncthreads();
        if (k0 + 8 < K) {
            a_pre = *reinterpret_cast<const float4*>(Ag + k0 + 8);
            b_pre = *reinterpret_cast<const float4*>(Bg + (size_t)(k0 + 8) * N);
        }
        #pragma unroll
        for (int kk = 0; kk < 8; kk++) {
            float ar[8], br[8];
            *reinterpret_cast<float4*>(ar)     = *reinterpret_cast<const float4*>(&As[kk][ty*8]);
            *reinterpret_cast<float4*>(ar + 4) = *reinterpret_cast<const float4*>(&As[kk][ty*8+4]);
            *reinterpret_cast<float4*>(br)     = *reinterpret_cast<const float4*>(&Bs[kk][tx*8]);
            *reinterpret_cast<float4*>(br + 4) = *reinterpret_cast<const float4*>(&Bs[kk][tx*8+4]);
            #pragma unroll
            for (int i = 0; i < 8; i++)
                #pragma unroll
                for (int j = 0; j < 8; j++)
                    acc[i][j] = fmaf(ar[i], br[j], acc[i][j]);
        }
        __syncthreads();
    }

    int btrow = m0 + ty * 8;
    int cbase = n0 + tx * 8;
    #pragma unroll
    for (int i = 0; i < 8; i++) {
        int bt = btrow + i;
        const float4* xr = reinterpret_cast<const float4*>(xres + (size_t)bt * D_ + cbase);
        const float4* bb = reinterpret_cast<const float4*>(bias + cbase);
        float4 x0 = xr[0], x1 = xr[1];
        float4 b0 = bb[0], b1 = bb[1];
        float4 o0 = make_float4(acc[i][0]+b0.x+x0.x, acc[i][1]+b0.y+x0.y,
                                acc[i][2]+b0.z+x0.z, acc[i][3]+b0.w+x0.w);
        float4 o1 = make_float4(acc[i][4]+b1.x+x1.x, acc[i][5]+b1.y+x1.y,
                                acc[i][6]+b1.z+x1.z, acc[i][7]+b1.w+x1.w);
        float4* op = reinterpret_cast<float4*>(out + (size_t)bt * D_ + cbase);
        op[0] = o0; op[1] = o1;
    }
}

// ======================= launch ============================================
extern "C" void kernel_launch(void* const* d_in, const int* in_sizes, int n_in,
                              void* d_out, int out_size) {
    const float* x      = (const float*)d_in[0];
    const float* w_qkv  = (const float*)d_in[1];
    const float* b_qkv  = (const float*)d_in[2];
    const float* w_proj = (const float*)d_in[3];
    const float* b_proj = (const float*)d_in[4];
    const float* gamma  = (const float*)d_in[5];
    const float* beta   = (const float*)d_in[6];
    float* out = (float*)d_out;

    cudaFuncSetAttribute(attn_kernel,
                         cudaFuncAttributeMaxDynamicSharedMemorySize, ATTN_SMEM);

    ln_kernel<<<BT_, 256>>>(x, gamma, beta);
    qkv_gemm<<<dim3(3 * D_ / 128, BT_ / 128), 256>>>(w_qkv, b_qkv);
    attn_kernel<<<dim3(T_ / 128, H_, B_), 256, ATTN_SMEM>>>();
    proj_gemm<<<dim3(D_ / 128, BT_ / 128), 256>>>(w_proj, b_proj, x, out);
}

// round 5
// speedup vs baseline: 2.1098x; 2.1098x over previous
#include <cuda_runtime.h>
#include <math.h>
#include <stdint.h>

// Problem dims
#define B_   4
#define T_   2048
#define D_   1024
#define H_   16
#define HD_  64
#define BT_  (B_*T_)          // 8192 rows

// ---------------- scratch (device globals: no runtime allocation) ----------
__device__ float g_xn[BT_*D_];   // layernorm output       [BT, D]
__device__ float g_q [BT_*D_];   // Q  [B,H,T,HD]
__device__ float g_k [BT_*D_];   // K  [B,H,T,HD]
__device__ float g_v [BT_*D_];   // V  [B,H,T,HD]
__device__ float g_ao[BT_*D_];   // attention out          [B,T,D]

// ---------------- tf32 helpers ---------------------------------------------
__device__ __forceinline__ uint32_t f2tf32(float x) {
    uint32_t r;
    asm("cvt.rna.tf32.f32 %0, %1;" : "=r"(r) : "f"(x));   // round-to-nearest: unbiased!
    return r;
}

// D = A(16x8, row) * B(8x8, col) + D   (tf32 in, f32 accum)
__device__ __forceinline__ void mma_tf32(float* c, const uint32_t* a, const uint32_t* b) {
    asm volatile(
        "mma.sync.aligned.m16n8k8.row.col.f32.tf32.tf32.f32 "
        "{%0,%1,%2,%3}, {%4,%5,%6,%7}, {%8,%9}, {%0,%1,%2,%3};\n"
        : "+f"(c[0]), "+f"(c[1]), "+f"(c[2]), "+f"(c[3])
        : "r"(a[0]), "r"(a[1]), "r"(a[2]), "r"(a[3]), "r"(b[0]), "r"(b[1]));
}

// ======================= LayerNorm =========================================
__global__ void ln_kernel(const float* __restrict__ x,
                          const float* __restrict__ gamma,
                          const float* __restrict__ beta) {
    int row = blockIdx.x;
    int tid = threadIdx.x;                         // 256 threads, 4 floats each
    const float4* xr = reinterpret_cast<const float4*>(x + (size_t)row * D_);
    float4 v = xr[tid];
    float s  = v.x + v.y + v.z + v.w;
    float sq = v.x*v.x + v.y*v.y + v.z*v.z + v.w*v.w;
    #pragma unroll
    for (int o = 16; o > 0; o >>= 1) {
        s  += __shfl_xor_sync(0xffffffffu, s,  o);
        sq += __shfl_xor_sync(0xffffffffu, sq, o);
    }
    __shared__ float ss[8], sq2[8];
    __shared__ float mu_s, rs_s;
    if ((tid & 31) == 0) { ss[tid >> 5] = s; sq2[tid >> 5] = sq; }
    __syncthreads();
    if (tid == 0) {
        float a = 0.f, b2 = 0.f;
        #pragma unroll
        for (int i = 0; i < 8; i++) { a += ss[i]; b2 += sq2[i]; }
        float mu  = a * (1.0f / D_);
        float var = b2 * (1.0f / D_) - mu * mu;
        mu_s = mu;
        rs_s = rsqrtf(var + 1e-5f);
    }
    __syncthreads();
    float mu = mu_s, rs = rs_s;
    float4 g  = reinterpret_cast<const float4*>(gamma)[tid];
    float4 be = reinterpret_cast<const float4*>(beta)[tid];
    float4 o;
    o.x = (v.x - mu) * rs * g.x + be.x;
    o.y = (v.y - mu) * rs * g.y + be.y;
    o.z = (v.z - mu) * rs * g.z + be.z;
    o.w = (v.w - mu) * rs * g.w + be.w;
    reinterpret_cast<float4*>(g_xn + (size_t)row * D_)[tid] = o;
}

// ======================= QKV GEMM (tf32 tensor core, 128x128x16) ===========
// C = g_xn[8192,1024] @ w_qkv[1024,3072] + b_qkv ; scatter to q/k/v [B,H,T,HD]
// 8 warps: 2 (m) x 4 (n); warp tile 64x32; mma m16n8k8.
__global__ __launch_bounds__(256, 2) void qkv_gemm(const float* __restrict__ Bw,
                                                   const float* __restrict__ bias) {
    const int N = 3 * D_, K = D_;
    __shared__ uint32_t As[128][20];   // [m][k], stride 20 -> conflict-free frag loads
    __shared__ uint32_t Bs[16][132];   // [k][n], stride 132
    int tid  = threadIdx.x;
    int lane = tid & 31, wid = tid >> 5;
    int warp_m = (wid & 1) * 64, warp_n = (wid >> 1) * 32;
    int m0 = blockIdx.y * 128, n0 = blockIdx.x * 128;

    int arow = tid >> 1, acol = (tid & 1) * 8;
    int brow = tid >> 4, bcol = (tid & 15) * 8;
    const float* Ag = g_xn + (size_t)(m0 + arow) * K + acol;
    const float* Bg = Bw + (size_t)brow * N + n0 + bcol;

    float4 pa0 = *reinterpret_cast<const float4*>(Ag);
    float4 pa1 = *reinterpret_cast<const float4*>(Ag + 4);
    float4 pb0 = *reinterpret_cast<const float4*>(Bg);
    float4 pb1 = *reinterpret_cast<const float4*>(Bg + 4);

    float acc[4][4][4] = {};

    for (int k0 = 0; k0 < K; k0 += 16) {
        As[arow][acol+0] = f2tf32(pa0.x); As[arow][acol+1] = f2tf32(pa0.y);
        As[arow][acol+2] = f2tf32(pa0.z); As[arow][acol+3] = f2tf32(pa0.w);
        As[arow][acol+4] = f2tf32(pa1.x); As[arow][acol+5] = f2tf32(pa1.y);
        As[arow][acol+6] = f2tf32(pa1.z); As[arow][acol+7] = f2tf32(pa1.w);
        Bs[brow][bcol+0] = f2tf32(pb0.x); Bs[brow][bcol+1] = f2tf32(pb0.y);
        Bs[brow][bcol+2] = f2tf32(pb0.z); Bs[brow][bcol+3] = f2tf32(pb0.w);
        Bs[brow][bcol+4] = f2tf32(pb1.x); Bs[brow][bcol+5] = f2tf32(pb1.y);
        Bs[brow][bcol+6] = f2tf32(pb1.z); Bs[brow][bcol+7] = f2tf32(pb1.w);
        __syncthreads();
        if (k0 + 16 < K) {
            pa0 = *reinterpret_cast<const float4*>(Ag + k0 + 16);
            pa1 = *reinterpret_cast<const float4*>(Ag + k0 + 20);
            pb0 = *reinterpret_cast<const float4*>(Bg + (size_t)(k0 + 16) * N);
            pb1 = *reinterpret_cast<const float4*>(Bg + (size_t)(k0 + 16) * N + 4);
        }
        #pragma unroll
        for (int ks = 0; ks < 16; ks += 8) {
            uint32_t af[4][4], bf[4][2];
            int kc = ks + (lane & 3);
            int rq = warp_m + (lane >> 2);
            #pragma unroll
            for (int mt = 0; mt < 4; mt++) {
                int r = rq + mt * 16;
                af[mt][0] = As[r    ][kc    ];
                af[mt][1] = As[r + 8][kc    ];
                af[mt][2] = As[r    ][kc + 4];
                af[mt][3] = As[r + 8][kc + 4];
            }
            #pragma unroll
            for (int nt = 0; nt < 4; nt++) {
                int nn = warp_n + nt * 8 + (lane >> 2);
                bf[nt][0] = Bs[kc    ][nn];
                bf[nt][1] = Bs[kc + 4][nn];
            }
            #pragma unroll
            for (int mt = 0; mt < 4; mt++)
                #pragma unroll
                for (int nt = 0; nt < 4; nt++)
                    mma_tf32(acc[mt][nt], af[mt], bf[nt]);
        }
        __syncthreads();
    }

    // epilogue: bias + scatter to q/k/v [B,H,T,HD]
    #pragma unroll
    for (int mt = 0; mt < 4; mt++) {
        #pragma unroll
        for (int half = 0; half < 2; half++) {
            int bt = m0 + warp_m + mt * 16 + (lane >> 2) + half * 8;
            int bb = bt >> 11;        // /2048
            int t  = bt & 2047;
            #pragma unroll
            for (int nt = 0; nt < 4; nt++) {
                int c = n0 + warp_n + nt * 8 + (lane & 3) * 2;
                float v0 = acc[mt][nt][half*2+0] + bias[c];
                float v1 = acc[mt][nt][half*2+1] + bias[c+1];
                int s   = c >> 10;    // 0=q,1=k,2=v
                int rem = c & 1023;
                int hh  = rem >> 6;
                int d   = rem & 63;   // even -> float2 aligned
                float* dst = (s == 0) ? g_q : ((s == 1) ? g_k : g_v);
                *reinterpret_cast<float2*>(
                    &dst[((size_t)((bb * H_ + hh) * T_) + t) * HD_ + d]) =
                    make_float2(v0, v1);
            }
        }
    }
}

// ======================= Flash Attention (tf32 tensor core) ================
// Per block: one (b, h, 128-row q tile). 256 threads = 8 warps (2m x 4n).
// smem: Qs[128][68] tf32, Ks[128][68] tf32, Vt[64][132] tf32 (V transposed),
//       Ss[128][132] f32 (S then P-tf32 bits), alpha[128], linv[128].
#define ATTN_SMEM 172032

__global__ __launch_bounds__(256, 1) void attn_kernel() {
    extern __shared__ char smraw[];
    uint32_t* Qs = reinterpret_cast<uint32_t*>(smraw);   // 128*68
    uint32_t* Ks = Qs + 128 * 68;                        // 128*68
    uint32_t* Vt = Ks + 128 * 68;                        // 64*132
    float*    Ss = reinterpret_cast<float*>(Vt + 64 * 132);  // 128*132
    float* alpha_s = Ss + 128 * 132;                     // 128
    float* linv_s  = alpha_s + 128;                      // 128

    int tid  = threadIdx.x;
    int lane = tid & 31, wid = tid >> 5;
    int warp_m  = (wid & 1) * 64;     // q rows
    int warp_n  = (wid >> 1) * 32;    // key cols (S)
    int warp_np = (wid >> 1) * 16;    // d cols (PV)

    int qtile = blockIdx.x, h = blockIdx.y, b = blockIdx.z;
    size_t bh = (size_t)(b * H_ + h) * T_ * HD_;
    const float* Qg = g_q + bh + (size_t)qtile * 128 * HD_;

    // Load Q tile (row-major, tf32 bits)
    for (int i = tid; i < 128 * 16; i += 256) {
        int row = i >> 4, c4 = (i & 15) * 4;
        float4 f = *reinterpret_cast<const float4*>(Qg + row * HD_ + c4);
        Qs[row * 68 + c4 + 0] = f2tf32(f.x);
        Qs[row * 68 + c4 + 1] = f2tf32(f.y);
        Qs[row * 68 + c4 + 2] = f2tf32(f.z);
        Qs[row * 68 + c4 + 3] = f2tf32(f.w);
    }

    float O[4][2][4] = {};           // persistent PV accumulators
    float m_run = -1e30f, l_run = 0.f;
    int srow = tid >> 1, shalf = tid & 1;

    for (int kt = 0; kt < 16; kt++) {
        __syncthreads();             // prev PV done before Ks/Vt/Ss reuse
        const float* Kg = g_k + bh + (size_t)kt * 128 * HD_;
        const float* Vg = g_v + bh + (size_t)kt * 128 * HD_;
        for (int i = tid; i < 128 * 16; i += 256) {
            int row = i >> 4, c4 = (i & 15) * 4;
            float4 f = *reinterpret_cast<const float4*>(Kg + row * HD_ + c4);
            Ks[row * 68 + c4 + 0] = f2tf32(f.x);
            Ks[row * 68 + c4 + 1] = f2tf32(f.y);
            Ks[row * 68 + c4 + 2] = f2tf32(f.z);
            Ks[row * 68 + c4 + 3] = f2tf32(f.w);
            float4 g2 = *reinterpret_cast<const float4*>(Vg + row * HD_ + c4);
            Vt[(c4 + 0) * 132 + row] = f2tf32(g2.x);
            Vt[(c4 + 1) * 132 + row] = f2tf32(g2.y);
            Vt[(c4 + 2) * 132 + row] = f2tf32(g2.z);
            Vt[(c4 + 3) * 132 + row] = f2tf32(g2.w);
        }
        __syncthreads();

        // ---- S = Q K^T (128x128, k=64) via mma -----------------------------
        float sacc[4][4][4] = {};
        #pragma unroll
        for (int ks = 0; ks < 64; ks += 8) {
            uint32_t af[4][4], bf[4][2];
            int kc = ks + (lane & 3);
            int rq = warp_m + (lane >> 2);
            #pragma unroll
            for (int mt = 0; mt < 4; mt++) {
                int r = rq + mt * 16;
                af[mt][0] = Qs[r * 68 + kc];
                af[mt][1] = Qs[(r + 8) * 68 + kc];
                af[mt][2] = Qs[r * 68 + kc + 4];
                af[mt][3] = Qs[(r + 8) * 68 + kc + 4];
            }
            #pragma unroll
            for (int nt = 0; nt < 4; nt++) {
                int nn = warp_n + nt * 8 + (lane >> 2);
                bf[nt][0] = Ks[nn * 68 + kc];
                bf[nt][1] = Ks[nn * 68 + kc + 4];
            }
            #pragma unroll
            for (int mt = 0; mt < 4; mt++)
                #pragma unroll
                for (int nt = 0; nt < 4; nt++)
                    mma_tf32(sacc[mt][nt], af[mt], bf[nt]);
        }
        const float scale = 0.125f;   // HD^-0.5
        #pragma unroll
        for (int mt = 0; mt < 4; mt++) {
            int r = warp_m + mt * 16 + (lane >> 2);
            #pragma unroll
            for (int nt = 0; nt < 4; nt++) {
                int c = warp_n + nt * 8 + (lane & 3) * 2;
                Ss[r * 132 + c]           = sacc[mt][nt][0] * scale;
                Ss[r * 132 + c + 1]       = sacc[mt][nt][1] * scale;
                Ss[(r + 8) * 132 + c]     = sacc[mt][nt][2] * scale;
                Ss[(r + 8) * 132 + c + 1] = sacc[mt][nt][3] * scale;
            }
        }
        __syncthreads();

        // ---- online softmax: 2 threads per row, 64 cols each ---------------
        float* Srow = Ss + srow * 132 + shalf * 64;
        float mloc = -1e30f;
        #pragma unroll 4
        for (int j = 0; j < 64; j++) mloc = fmaxf(mloc, Srow[j]);
        mloc = fmaxf(mloc, __shfl_xor_sync(0xffffffffu, mloc, 1));
        float m_new = fmaxf(m_run, mloc);
        float al = __expf(m_run - m_new);
        float sl = 0.f;
        #pragma unroll 4
        for (int j = 0; j < 64; j++) {
            float p = __expf(Srow[j] - m_new);
            Srow[j] = __uint_as_float(f2tf32(p));    // store P as tf32 bits
            sl += p;
        }
        sl += __shfl_xor_sync(0xffffffffu, sl, 1);
        l_run = l_run * al + sl;
        m_run = m_new;
        if (shalf == 0) alpha_s[srow] = al;
        __syncthreads();

        // ---- O = O*alpha + P V (128x64, k=128) via mma ---------------------
        #pragma unroll
        for (int mt = 0; mt < 4; mt++) {
            int r = warp_m + mt * 16 + (lane >> 2);
            float a0 = alpha_s[r], a1 = alpha_s[r + 8];
            #pragma unroll
            for (int nt = 0; nt < 2; nt++) {
                O[mt][nt][0] *= a0; O[mt][nt][1] *= a0;
                O[mt][nt][2] *= a1; O[mt][nt][3] *= a1;
            }
        }
        #pragma unroll
        for (int ks = 0; ks < 128; ks += 8) {
            uint32_t pa[4][4], pb[2][2];
            int kc = ks + (lane & 3);
            #pragma unroll
            for (int mt = 0; mt < 4; mt++) {
                int r = warp_m + mt * 16 + (lane >> 2);
                pa[mt][0] = __float_as_uint(Ss[r * 132 + kc]);
                pa[mt][1] = __float_as_uint(Ss[(r + 8) * 132 + kc]);
                pa[mt][2] = __float_as_uint(Ss[r * 132 + kc + 4]);
                pa[mt][3] = __float_as_uint(Ss[(r + 8) * 132 + kc + 4]);
            }
            #pragma unroll
            for (int nt = 0; nt < 2; nt++) {
                int nn = warp_np + nt * 8 + (lane >> 2);
                pb[nt][0] = Vt[nn * 132 + kc];
                pb[nt][1] = Vt[nn * 132 + kc + 4];
            }
            #pragma unroll
            for (int mt = 0; mt < 4; mt++)
                #pragma unroll
                for (int nt = 0; nt < 2; nt++)
                    mma_tf32(O[mt][nt], pa[mt], pb[nt]);
        }
    }

    if (shalf == 0) linv_s[srow] = 1.f / l_run;
    __syncthreads();

    // write to g_ao [B,T,D], d = h*64 + col
    size_t outbase = ((size_t)b * T_ + qtile * 128) * D_ + h * HD_;
    #pragma unroll
    for (int mt = 0; mt < 4; mt++) {
        #pragma unroll
        for (int half = 0; half < 2; half++) {
            int r = warp_m + mt * 16 + (lane >> 2) + half * 8;
            float li = linv_s[r];
            #pragma unroll
            for (int nt = 0; nt < 2; nt++) {
                int c = warp_np + nt * 8 + (lane & 3) * 2;
                *reinterpret_cast<float2*>(&g_ao[outbase + (size_t)r * D_ + c]) =
                    make_float2(O[mt][nt][half*2] * li, O[mt][nt][half*2+1] * li);
            }
        }
    }
}

// ======================= Proj GEMM + bias + residual (tf32 TC) =============
__global__ __launch_bounds__(256, 2) void proj_gemm(const float* __restrict__ Bw,
                                                    const float* __restrict__ bias,
                                                    const float* __restrict__ xres,
                                                    float* __restrict__ out) {
    const int N = D_, K = D_;
    __shared__ uint32_t As[128][20];
    __shared__ uint32_t Bs[16][132];
    int tid  = threadIdx.x;
    int lane = tid & 31, wid = tid >> 5;
    int warp_m = (wid & 1) * 64, warp_n = (wid >> 1) * 32;
    int m0 = blockIdx.y * 128, n0 = blockIdx.x * 128;

    int arow = tid >> 1, acol = (tid & 1) * 8;
    int brow = tid >> 4, bcol = (tid & 15) * 8;
    const float* Ag = g_ao + (size_t)(m0 + arow) * K + acol;
    const float* Bg = Bw + (size_t)brow * N + n0 + bcol;

    float4 pa0 = *reinterpret_cast<const float4*>(Ag);
    float4 pa1 = *reinterpret_cast<const float4*>(Ag + 4);
    float4 pb0 = *reinterpret_cast<const float4*>(Bg);
    float4 pb1 = *reinterpret_cast<const float4*>(Bg + 4);

    float acc[4][4][4] = {};

    for (int k0 = 0; k0 < K; k0 += 16) {
        As[arow][acol+0] = f2tf32(pa0.x); As[arow][acol+1] = f2tf32(pa0.y);
        As[arow][acol+2] = f2tf32(pa0.z); As[arow][acol+3] = f2tf32(pa0.w);
        As[arow][acol+4] = f2tf32(pa1.x); As[arow][acol+5] = f2tf32(pa1.y);
        As[arow][acol+6] = f2tf32(pa1.z); As[arow][acol+7] = f2tf32(pa1.w);
        Bs[brow][bcol+0] = f2tf32(pb0.x); Bs[brow][bcol+1] = f2tf32(pb0.y);
        Bs[brow][bcol+2] = f2tf32(pb0.z); Bs[brow][bcol+3] = f2tf32(pb0.w);
        Bs[brow][bcol+4] = f2tf32(pb1.x); Bs[brow][bcol+5] = f2tf32(pb1.y);
        Bs[brow][bcol+6] = f2tf32(pb1.z); Bs[brow][bcol+7] = f2tf32(pb1.w);
        __syncthreads();
        if (k0 + 16 < K) {
            pa0 = *reinterpret_cast<const float4*>(Ag + k0 + 16);
            pa1 = *reinterpret_cast<const float4*>(Ag + k0 + 20);
            pb0 = *reinterpret_cast<const float4*>(Bg + (size_t)(k0 + 16) * N);
            pb1 = *reinterpret_cast<const float4*>(Bg + (size_t)(k0 + 16) * N + 4);
        }
        #pragma unroll
        for (int ks = 0; ks < 16; ks += 8) {
            uint32_t af[4][4], bf[4][2];
            int kc = ks + (lane & 3);
            int rq = warp_m + (lane >> 2);
            #pragma unroll
            for (int mt = 0; mt < 4; mt++) {
                int r = rq + mt * 16;
                af[mt][0] = As[r    ][kc    ];
                af[mt][1] = As[r + 8][kc    ];
                af[mt][2] = As[r    ][kc + 4];
                af[mt][3] = As[r + 8][kc + 4];
            }
            #pragma unroll
            for (int nt = 0; nt < 4; nt++) {
                int nn = warp_n + nt * 8 + (lane >> 2);
                bf[nt][0] = Bs[kc    ][nn];
                bf[nt][1] = Bs[kc + 4][nn];
            }
            #pragma unroll
            for (int mt = 0; mt < 4; mt++)
                #pragma unroll
                for (int nt = 0; nt < 4; nt++)
                    mma_tf32(acc[mt][nt], af[mt], bf[nt]);
        }
        __syncthreads();
    }

    // epilogue: bias + residual
    #pragma unroll
    for (int mt = 0; mt < 4; mt++) {
        #pragma unroll
        for (int half = 0; half < 2; half++) {
            int row = m0 + warp_m + mt * 16 + (lane >> 2) + half * 8;
            #pragma unroll
            for (int nt = 0; nt < 4; nt++) {
                int c = n0 + warp_n + nt * 8 + (lane & 3) * 2;
                float2 bi = *reinterpret_cast<const float2*>(&bias[c]);
                float2 xr = *reinterpret_cast<const float2*>(&xres[(size_t)row * D_ + c]);
                float2 o;
                o.x = acc[mt][nt][half*2+0] + bi.x + xr.x;
                o.y = acc[mt][nt][half*2+1] + bi.y + xr.y;
                *reinterpret_cast<float2*>(&out[(size_t)row * D_ + c]) = o;
            }
        }
    }
}

// ======================= launch ============================================
extern "C" void kernel_launch(void* const* d_in, const int* in_sizes, int n_in,
                              void* d_out, int out_size) {
    const float* x      = (const float*)d_in[0];
    const float* w_qkv  = (const float*)d_in[1];
    const float* b_qkv  = (const float*)d_in[2];
    const float* w_proj = (const float*)d_in[3];
    const float* b_proj = (const float*)d_in[4];
    const float* gamma  = (const float*)d_in[5];
    const float* beta   = (const float*)d_in[6];
    float* out = (float*)d_out;

    cudaFuncSetAttribute(attn_kernel,
                         cudaFuncAttributeMaxDynamicSharedMemorySize, ATTN_SMEM);

    ln_kernel<<<BT_, 256>>>(x, gamma, beta);
    qkv_gemm<<<dim3(3 * D_ / 128, BT_ / 128), 256>>>(w_qkv, b_qkv);
    attn_kernel<<<dim3(T_ / 128, H_, B_), 256, ATTN_SMEM>>>();
    proj_gemm<<<dim3(D_ / 128, BT_ / 128), 256>>>(w_proj, b_proj, x, out);
}

// round 9
// speedup vs baseline: 3.0953x; 1.4671x over previous
#include <cuda_runtime.h>
#include <cuda_bf16.h>
#include <math.h>
#include <stdint.h>

// Problem dims
#define B_   4
#define T_   2048
#define D_   1024
#define H_   16
#define HD_  64
#define BT_  (B_*T_)          // 8192 rows

typedef __nv_bfloat16 bf16;

// ---------------- scratch (device globals: no runtime allocation) ----------
__device__ bf16 g_xnh[BT_*D_];     // layernorm output bf16   [BT, D]
__device__ bf16 g_wqT[3*D_*D_];    // w_qkv transposed bf16   [3D, D] (n-major, k contiguous)
__device__ bf16 g_wpT[D_*D_];      // w_proj transposed bf16  [D, D]
__device__ bf16 g_q [BT_*D_];      // Q bf16 [B,H,T,HD]
__device__ bf16 g_k [BT_*D_];      // K bf16 [B,H,T,HD]
__device__ bf16 g_v [BT_*D_];      // V bf16 [B,H,T,HD]
__device__ bf16 g_aoh[BT_*D_];     // attention out bf16 [B,T,D]

// ---------------- helpers ---------------------------------------------------
__device__ __forceinline__ uint32_t pack_bf16(float lo, float hi) {
    uint32_t r;
    asm("cvt.rn.bf16x2.f32 %0, %1, %2;" : "=r"(r) : "f"(hi), "f"(lo));
    return r;
}
__device__ __forceinline__ void mma_bf16(float* c, const uint32_t* a, const uint32_t* b) {
    asm volatile(
        "mma.sync.aligned.m16n8k16.row.col.f32.bf16.bf16.f32 "
        "{%0,%1,%2,%3}, {%4,%5,%6,%7}, {%8,%9}, {%0,%1,%2,%3};\n"
        : "+f"(c[0]), "+f"(c[1]), "+f"(c[2]), "+f"(c[3])
        : "r"(a[0]), "r"(a[1]), "r"(a[2]), "r"(a[3]), "r"(b[0]), "r"(b[1]));
}
__device__ __forceinline__ void ldsm_x4(uint32_t* r, uint32_t addr) {
    asm volatile("ldmatrix.sync.aligned.m8n8.x4.shared.b16 {%0,%1,%2,%3}, [%4];"
        : "=r"(r[0]), "=r"(r[1]), "=r"(r[2]), "=r"(r[3]) : "r"(addr));
}
__device__ __forceinline__ void ldsm_x2(uint32_t* r, uint32_t addr) {
    asm volatile("ldmatrix.sync.aligned.m8n8.x2.shared.b16 {%0,%1}, [%2];"
        : "=r"(r[0]), "=r"(r[1]) : "r"(addr));
}
__device__ __forceinline__ void ldsm_x2t(uint32_t* r, uint32_t addr) {
    asm volatile("ldmatrix.sync.aligned.m8n8.x2.trans.shared.b16 {%0,%1}, [%2];"
        : "=r"(r[0]), "=r"(r[1]) : "r"(addr));
}
__device__ __forceinline__ void cpa16(uint32_t s, const void* g) {
    asm volatile("cp.async.cg.shared.global [%0], [%1], 16;\n" :: "r"(s), "l"(g));
}
#define CP_COMMIT() asm volatile("cp.async.commit_group;")

// ======================= weight transpose + bf16 convert ===================
__global__ void wtrans_qkv(const float* __restrict__ src) {   // [1024][3072]
    __shared__ float t[32][33];
    int c0 = blockIdx.x * 32, r0 = blockIdx.y * 32;
    int x = threadIdx.x, y = threadIdx.y;
    #pragma unroll
    for (int j = 0; j < 32; j += 8)
        t[y+j][x] = src[(size_t)(r0+y+j) * 3072 + c0 + x];
    __syncthreads();
    #pragma unroll
    for (int j = 0; j < 32; j += 8)
        g_wqT[(size_t)(c0+y+j) * 1024 + r0 + x] = __float2bfloat16(t[x][y+j]);
}
__global__ void wtrans_proj(const float* __restrict__ src) {  // [1024][1024]
    __shared__ float t[32][33];
    int c0 = blockIdx.x * 32, r0 = blockIdx.y * 32;
    int x = threadIdx.x, y = threadIdx.y;
    #pragma unroll
    for (int j = 0; j < 32; j += 8)
        t[y+j][x] = src[(size_t)(r0+y+j) * 1024 + c0 + x];
    __syncthreads();
    #pragma unroll
    for (int j = 0; j < 32; j += 8)
        g_wpT[(size_t)(c0+y+j) * 1024 + r0 + x] = __float2bfloat16(t[x][y+j]);
}

// ======================= LayerNorm (bf16 out) ==============================
__global__ void ln_kernel(const float* __restrict__ x,
                          const float* __restrict__ gamma,
                          const float* __restrict__ beta) {
    int row = blockIdx.x;
    int tid = threadIdx.x;                         // 256 threads, 4 floats each
    const float4* xr = reinterpret_cast<const float4*>(x + (size_t)row * D_);
    float4 v = xr[tid];
    float s  = v.x + v.y + v.z + v.w;
    float sq = v.x*v.x + v.y*v.y + v.z*v.z + v.w*v.w;
    #pragma unroll
    for (int o = 16; o > 0; o >>= 1) {
        s  += __shfl_xor_sync(0xffffffffu, s,  o);
        sq += __shfl_xor_sync(0xffffffffu, sq, o);
    }
    __shared__ float ss[8], sq2[8];
    __shared__ float mu_s, rs_s;
    if ((tid & 31) == 0) { ss[tid >> 5] = s; sq2[tid >> 5] = sq; }
    __syncthreads();
    if (tid == 0) {
        float a = 0.f, b2 = 0.f;
        #pragma unroll
        for (int i = 0; i < 8; i++) { a += ss[i]; b2 += sq2[i]; }
        float mu  = a * (1.0f / D_);
        float var = b2 * (1.0f / D_) - mu * mu;
        mu_s = mu;
        rs_s = rsqrtf(var + 1e-5f);
    }
    __syncthreads();
    float mu = mu_s, rs = rs_s;
    float4 g  = reinterpret_cast<const float4*>(gamma)[tid];
    float4 be = reinterpret_cast<const float4*>(beta)[tid];
    float o0 = (v.x - mu) * rs * g.x + be.x;
    float o1 = (v.y - mu) * rs * g.y + be.y;
    float o2 = (v.z - mu) * rs * g.z + be.z;
    float o3 = (v.w - mu) * rs * g.w + be.w;
    uint2 packed = make_uint2(pack_bf16(o0, o1), pack_bf16(o2, o3));
    *reinterpret_cast<uint2*>(g_xnh + (size_t)row * D_ + tid * 4) = packed;
}

// ======================= bf16 GEMM core (128x128 tile, BK=64, cp.async) ====
// A: [M][1024] bf16 row-major. B: [N][1024] bf16 (n-major, k contiguous).
// row stride 144 B (72 halves). stage stride 18432 B. A: [0,36864), B: [36864,73728).
__device__ __forceinline__ void gemm_core_bf16(
    const bf16* __restrict__ Agm, const bf16* __restrict__ Bgm,
    int m0, int n0, float acc[4][4][4])
{
    extern __shared__ uint32_t smem_u[];
    uint32_t smem_b = (uint32_t)__cvta_generic_to_shared(smem_u);
    int tid = threadIdx.x, lane = tid & 31, wid = tid >> 5;
    int warp_m = (wid & 1) * 64, warp_n = (wid >> 1) * 32;
    int lrow = tid & 127, lpart = tid >> 7;        // 0/1 -> halves of the 128B k-row

    const bf16* ag = Agm + (size_t)(m0 + lrow) * D_ + lpart * 32;
    const bf16* bg = Bgm + (size_t)(n0 + lrow) * D_ + lpart * 32;
    uint32_t sa = smem_b + lrow * 144 + lpart * 64;            // A stage0
    uint32_t sb = smem_b + 36864 + lrow * 144 + lpart * 64;    // B stage0

    #pragma unroll
    for (int j = 0; j < 4; j++) {
        cpa16(sa + j * 16, ag + j * 8);
        cpa16(sb + j * 16, bg + j * 8);
    }
    CP_COMMIT();

    uint32_t a_lane = smem_b + (warp_m + (lane & 15)) * 144 + ((lane >> 4) << 4);
    uint32_t b_lane = smem_b + 36864 + (warp_n + (lane & 7)) * 144 + (((lane >> 3) & 1) << 4);

    for (int it = 0; it < 16; it++) {
        if (it < 15) {
            int st = (it + 1) & 1;
            const bf16* agn = ag + (it + 1) * 64;
            const bf16* bgn = bg + (it + 1) * 64;
            uint32_t san = sa + st * 18432;
            uint32_t sbn = sb + st * 18432;
            #pragma unroll
            for (int j = 0; j < 4; j++) {
                cpa16(san + j * 16, agn + j * 8);
                cpa16(sbn + j * 16, bgn + j * 8);
            }
            CP_COMMIT();
            asm volatile("cp.async.wait_group 1;");
        } else {
            asm volatile("cp.async.wait_group 0;");
        }
        __syncthreads();
        uint32_t ab = a_lane + (it & 1) * 18432;
        uint32_t bb = b_lane + (it & 1) * 18432;
        #pragma unroll
        for (int c = 0; c < 4; c++) {                 // 4 chunks of k16
            uint32_t af[4][4], bfr[4][2];
            #pragma unroll
            for (int mt = 0; mt < 4; mt++) ldsm_x4(af[mt], ab + mt * 2304 + c * 32);
            #pragma unroll
            for (int nt = 0; nt < 4; nt++) ldsm_x2(bfr[nt], bb + nt * 1152 + c * 32);
            #pragma unroll
            for (int mt = 0; mt < 4; mt++)
                #pragma unroll
                for (int nt = 0; nt < 4; nt++)
                    mma_bf16(acc[mt][nt], af[mt], bfr[nt]);
        }
        __syncthreads();
    }
}

#define GEMM_SMEM 73728

// ======================= QKV GEMM ==========================================
__global__ __launch_bounds__(256, 2) void qkv_gemm(const float* __restrict__ bias) {
    float acc[4][4][4] = {};
    int m0 = blockIdx.y * 128, n0 = blockIdx.x * 128;
    gemm_core_bf16(g_xnh, g_wqT, m0, n0, acc);

    int lane = threadIdx.x & 31, wid = threadIdx.x >> 5;
    int warp_m = (wid & 1) * 64, warp_n = (wid >> 1) * 32;
    #pragma unroll
    for (int mt = 0; mt < 4; mt++) {
        #pragma unroll
        for (int half = 0; half < 2; half++) {
            int bt = m0 + warp_m + mt * 16 + (lane >> 2) + half * 8;
            int bb = bt >> 11;
            int t  = bt & 2047;
            #pragma unroll
            for (int nt = 0; nt < 4; nt++) {
                int c = n0 + warp_n + nt * 8 + (lane & 3) * 2;
                float v0 = acc[mt][nt][half*2+0] + bias[c];
                float v1 = acc[mt][nt][half*2+1] + bias[c+1];
                int s   = c >> 10;
                int rem = c & 1023;
                int hh  = rem >> 6;
                int d   = rem & 63;
                bf16* dst = (s == 0) ? g_q : ((s == 1) ? g_k : g_v);
                *reinterpret_cast<uint32_t*>(
                    &dst[((size_t)((bb * H_ + hh) * T_) + t) * HD_ + d]) =
                    pack_bf16(v0, v1);
            }
        }
    }
}

// ======================= Proj GEMM + bias + residual =======================
__global__ __launch_bounds__(256, 2) void proj_gemm(const float* __restrict__ bias,
                                                    const float* __restrict__ xres,
                                                    float* __restrict__ out) {
    float acc[4][4][4] = {};
    int m0 = blockIdx.y * 128, n0 = blockIdx.x * 128;
    gemm_core_bf16(g_aoh, g_wpT, m0, n0, acc);

    int lane = threadIdx.x & 31, wid = threadIdx.x >> 5;
    int warp_m = (wid & 1) * 64, warp_n = (wid >> 1) * 32;
    #pragma unroll
    for (int mt = 0; mt < 4; mt++) {
        #pragma unroll
        for (int half = 0; half < 2; half++) {
            int row = m0 + warp_m + mt * 16 + (lane >> 2) + half * 8;
            #pragma unroll
            for (int nt = 0; nt < 4; nt++) {
                int c = n0 + warp_n + nt * 8 + (lane & 3) * 2;
                float2 bi = *reinterpret_cast<const float2*>(&bias[c]);
                float2 xr = *reinterpret_cast<const float2*>(&xres[(size_t)row * D_ + c]);
                float2 o;
                o.x = acc[mt][nt][half*2+0] + bi.x + xr.x;
                o.y = acc[mt][nt][half*2+1] + bi.y + xr.y;
                *reinterpret_cast<float2*>(&out[(size_t)row * D_ + c]) = o;
            }
        }
    }
}

// ======================= Flash Attention (bf16 TC, 512 threads) ============
// Per block: one (b, h, 128-q tile). 16 warps: 4(m: 32 rows) x 4(n).
// smem bytes:
//   Qs     [0, 18432)          128 x 72h bf16 (stride 144B)
//   Ks[2]  [18432, 55296)
//   Vs[2]  [55296, 92160)
//   Ss     [92160, 159744)     128 x 132 f32 (stride 528B), scores only
//   Ps     [159744, 194560)    128 x 68 u32 (stride 272B), packed bf16 P
//   alpha  [194560, 195072)
//   linv   [195072, 195584)
#define ATTN_SMEM 195584

__global__ __launch_bounds__(512, 1) void attn_kernel() {
    extern __shared__ char smraw[];
    uint32_t smem_b = (uint32_t)__cvta_generic_to_shared(smraw);
    float*    Ss      = reinterpret_cast<float*>(smraw + 92160);
    uint32_t* Ps      = reinterpret_cast<uint32_t*>(smraw + 159744);
    float*    alpha_s = reinterpret_cast<float*>(smraw + 194560);
    float*    linv_s  = reinterpret_cast<float*>(smraw + 195072);

    int tid  = threadIdx.x;
    int lane = tid & 31, wid = tid >> 5;
    int warp_m  = (wid & 3) * 32;     // q rows
    int warp_n  = (wid >> 2) * 32;    // key cols (S)
    int warp_np = (wid >> 2) * 16;    // d cols (PV)

    int qtile = blockIdx.x, h = blockIdx.y, b = blockIdx.z;
    size_t bh = (size_t)(b * H_ + h) * T_ * HD_;
    const bf16* Qg = g_q + bh + (size_t)qtile * 128 * HD_;
    const bf16* Kg0 = g_k + bh;
    const bf16* Vg0 = g_v + bh;

    int lrow = tid & 127, lpart = tid >> 7;     // lpart 0..3: 32B quarter of row

    // FIXED loader: each thread copies 32B (2x cpa16) per tensor.
    // Row = 128B: quarters at byte offsets {0,32,64,96}+{0,16}. Full coverage:
    // 512 thr x 32B = 16KB = tile size (was 16B/thread = half the tile!).
    {
        uint32_t dq = smem_b + lrow * 144 + lpart * 32;
        uint32_t dk = smem_b + 18432 + lrow * 144 + lpart * 32;
        uint32_t dv = smem_b + 55296 + lrow * 144 + lpart * 32;
        const bf16* sq = Qg  + lrow * 64 + lpart * 16;
        const bf16* sk = Kg0 + lrow * 64 + lpart * 16;
        const bf16* sv = Vg0 + lrow * 64 + lpart * 16;
        cpa16(dq, sq);       cpa16(dq + 16, sq + 8);
        cpa16(dk, sk);       cpa16(dk + 16, sk + 8);
        cpa16(dv, sv);       cpa16(dv + 16, sv + 8);
    }
    CP_COMMIT();

    // lane-invariant fragment address pieces
    uint32_t q_lane = smem_b + (warp_m + (lane & 15)) * 144 + ((lane >> 4) << 4);
    uint32_t k_lane = smem_b + 18432 + (warp_n + (lane & 7)) * 144 + (((lane >> 3) & 1) << 4);
    uint32_t p_lane = smem_b + 159744 + (warp_m + (lane & 15)) * 272 + ((lane >> 4) << 4);
    uint32_t v_lane = smem_b + 55296 + (lane & 15) * 144 + warp_np * 2;

    uint32_t qf[2][4][4];            // Q fragments, loaded once
    float O[2][2][4] = {};           // PV accumulators
    float m_run = -1e30f, l_run = 0.f;
    int srow = tid >> 2, squart = tid & 3;

    for (int kt = 0; kt < 16; kt++) {
        if (kt < 15) {
            int st = (kt + 1) & 1;
            const bf16* Kg = Kg0 + (size_t)(kt + 1) * 128 * HD_;
            const bf16* Vg = Vg0 + (size_t)(kt + 1) * 128 * HD_;
            uint32_t dk = smem_b + 18432 + st * 18432 + lrow * 144 + lpart * 32;
            uint32_t dv = smem_b + 55296 + st * 18432 + lrow * 144 + lpart * 32;
            const bf16* sk = Kg + lrow * 64 + lpart * 16;
            const bf16* sv = Vg + lrow * 64 + lpart * 16;
            cpa16(dk, sk);   cpa16(dk + 16, sk + 8);
            cpa16(dv, sv);   cpa16(dv + 16, sv + 8);
            CP_COMMIT();
            asm volatile("cp.async.wait_group 1;");
        } else {
            asm volatile("cp.async.wait_group 0;");
        }
        __syncthreads();

        if (kt == 0) {
            #pragma unroll
            for (int mt = 0; mt < 2; mt++)
                #pragma unroll
                for (int c = 0; c < 4; c++)
                    ldsm_x4(qf[mt][c], q_lane + mt * 2304 + c * 32);
        }
        int st = kt & 1;
        uint32_t kb = k_lane + st * 18432;
        uint32_t vb = v_lane + st * 18432;

        // ---- S = Q K^T (128x128, k=64) ------------------------------------
        float sacc[2][4][4] = {};
        #pragma unroll
        for (int c = 0; c < 4; c++) {
            uint32_t bfr[4][2];
            #pragma unroll
            for (int nt = 0; nt < 4; nt++) ldsm_x2(bfr[nt], kb + nt * 1152 + c * 32);
            #pragma unroll
            for (int mt = 0; mt < 2; mt++)
                #pragma unroll
                for (int nt = 0; nt < 4; nt++)
                    mma_bf16(sacc[mt][nt], qf[mt][c], bfr[nt]);
        }
        const float scale = 0.125f;   // HD^-0.5
        #pragma unroll
        for (int mt = 0; mt < 2; mt++) {
            int r = warp_m + mt * 16 + (lane >> 2);
            #pragma unroll
            for (int nt = 0; nt < 4; nt++) {
                int c = warp_n + nt * 8 + (lane & 3) * 2;
                Ss[r * 132 + c]           = sacc[mt][nt][0] * scale;
                Ss[r * 132 + c + 1]       = sacc[mt][nt][1] * scale;
                Ss[(r + 8) * 132 + c]     = sacc[mt][nt][2] * scale;
                Ss[(r + 8) * 132 + c + 1] = sacc[mt][nt][3] * scale;
            }
        }
        __syncthreads();

        // ---- online softmax: 4 threads per row, 32 cols each ---------------
        // Quarter q owns keys [32q,32q+32) = u32 slots [16q,16q+16) of Ps row.
        float* Srow = Ss + srow * 132 + squart * 32;
        uint32_t* Prow = Ps + srow * 68 + squart * 16;
        float mloc = -1e30f;
        #pragma unroll 4
        for (int j = 0; j < 32; j++) mloc = fmaxf(mloc, Srow[j]);
        mloc = fmaxf(mloc, __shfl_xor_sync(0xffffffffu, mloc, 1));
        mloc = fmaxf(mloc, __shfl_xor_sync(0xffffffffu, mloc, 2));
        float m_new = fmaxf(m_run, mloc);
        float al = __expf(m_run - m_new);
        float sl = 0.f;
        #pragma unroll 4
        for (int j = 0; j < 32; j += 2) {
            float p0 = __expf(Srow[j]   - m_new);
            float p1 = __expf(Srow[j+1] - m_new);
            sl += p0 + p1;
            Prow[j >> 1] = pack_bf16(p0, p1);
        }
        sl += __shfl_xor_sync(0xffffffffu, sl, 1);
        sl += __shfl_xor_sync(0xffffffffu, sl, 2);
        l_run = l_run * al + sl;
        m_run = m_new;
        if (squart == 0) alpha_s[srow] = al;
        __syncthreads();

        // ---- O = O*alpha + P V (128x64, k=128) -----------------------------
        #pragma unroll
        for (int mt = 0; mt < 2; mt++) {
            int r = warp_m + mt * 16 + (lane >> 2);
            float a0 = alpha_s[r], a1 = alpha_s[r + 8];
            #pragma unroll
            for (int nt = 0; nt < 2; nt++) {
                O[mt][nt][0] *= a0; O[mt][nt][1] *= a0;
                O[mt][nt][2] *= a1; O[mt][nt][3] *= a1;
            }
        }
        #pragma unroll
        for (int ks = 0; ks < 8; ks++) {          // k16 chunks over 128 keys
            uint32_t pa[2][4], pb[2][2];
            #pragma unroll
            for (int mt = 0; mt < 2; mt++)
                ldsm_x4(pa[mt], p_lane + mt * 4352 + ks * 32);
            #pragma unroll
            for (int nt = 0; nt < 2; nt++)
                ldsm_x2t(pb[nt], vb + ks * 2304 + nt * 16);
            #pragma unroll
            for (int mt = 0; mt < 2; mt++)
                #pragma unroll
                for (int nt = 0; nt < 2; nt++)
                    mma_bf16(O[mt][nt], pa[mt], pb[nt]);
        }
        __syncthreads();   // close this stage's buffers before reissue
    }

    if (squart == 0) linv_s[srow] = 1.f / l_run;
    __syncthreads();

    // write bf16 to g_aoh [B,T,D], d = h*64 + col
    size_t outbase = ((size_t)b * T_ + qtile * 128) * D_ + h * HD_;
    #pragma unroll
    for (int mt = 0; mt < 2; mt++) {
        #pragma unroll
        for (int half = 0; half < 2; half++) {
            int r = warp_m + mt * 16 + (lane >> 2) + half * 8;
            float li = linv_s[r];
            #pragma unroll
            for (int nt = 0; nt < 2; nt++) {
                int c = warp_np + nt * 8 + (lane & 3) * 2;
                *reinterpret_cast<uint32_t*>(&g_aoh[outbase + (size_t)r * D_ + c]) =
                    pack_bf16(O[mt][nt][half*2] * li, O[mt][nt][half*2+1] * li);
            }
        }
    }
}

// ======================= launch ============================================
extern "C" void kernel_launch(void* const* d_in, const int* in_sizes, int n_in,
                              void* d_out, int out_size) {
    const float* x      = (const float*)d_in[0];
    const float* w_qkv  = (const float*)d_in[1];
    const float* b_qkv  = (const float*)d_in[2];
    const float* w_proj = (const float*)d_in[3];
    const float* b_proj = (const float*)d_in[4];
    const float* gamma  = (const float*)d_in[5];
    const float* beta   = (const float*)d_in[6];
    float* out = (float*)d_out;

    cudaFuncSetAttribute(attn_kernel,
                         cudaFuncAttributeMaxDynamicSharedMemorySize, ATTN_SMEM);
    cudaFuncSetAttribute(qkv_gemm,
                         cudaFuncAttributeMaxDynamicSharedMemorySize, GEMM_SMEM);
    cudaFuncSetAttribute(proj_gemm,
                         cudaFuncAttributeMaxDynamicSharedMemorySize, GEMM_SMEM);

    wtrans_qkv<<<dim3(96, 32), dim3(32, 8)>>>(w_qkv);
    wtrans_proj<<<dim3(32, 32), dim3(32, 8)>>>(w_proj);
    ln_kernel<<<BT_, 256>>>(x, gamma, beta);
    qkv_gemm<<<dim3(24, 64), 256, GEMM_SMEM>>>(b_qkv);
    attn_kernel<<<dim3(T_ / 128, H_, B_), 512, ATTN_SMEM>>>();
    proj_gemm<<<dim3(8, 64), 256, GEMM_SMEM>>>(b_proj, x, out);
}

// round 10
// speedup vs baseline: 3.2015x; 1.0343x over previous
#include <cuda_runtime.h>
#include <cuda_bf16.h>
#include <math.h>
#include <stdint.h>

// Problem dims
#define B_   4
#define T_   2048
#define D_   1024
#define H_   16
#define HD_  64
#define BT_  (B_*T_)          // 8192 rows

typedef __nv_bfloat16 bf16;

// ---------------- scratch (device globals: no runtime allocation) ----------
__device__ bf16 g_xnh[BT_*D_];     // layernorm output bf16   [BT, D]
__device__ bf16 g_wqT[3*D_*D_];    // w_qkv transposed bf16   [3D, D] (n-major, k contiguous)
__device__ bf16 g_wpT[D_*D_];      // w_proj transposed bf16  [D, D]
__device__ bf16 g_q [BT_*D_];      // Q bf16 [B,H,T,HD]
__device__ bf16 g_k [BT_*D_];      // K bf16 [B,H,T,HD]
__device__ bf16 g_v [BT_*D_];      // V bf16 [B,H,T,HD]
__device__ bf16 g_aoh[BT_*D_];     // attention out bf16 [B,T,D]

// ---------------- helpers ---------------------------------------------------
__device__ __forceinline__ uint32_t pack_bf16(float lo, float hi) {
    uint32_t r;
    asm("cvt.rn.bf16x2.f32 %0, %1, %2;" : "=r"(r) : "f"(hi), "f"(lo));
    return r;
}
__device__ __forceinline__ void mma_bf16(float* c, const uint32_t* a, const uint32_t* b) {
    asm volatile(
        "mma.sync.aligned.m16n8k16.row.col.f32.bf16.bf16.f32 "
        "{%0,%1,%2,%3}, {%4,%5,%6,%7}, {%8,%9}, {%0,%1,%2,%3};\n"
        : "+f"(c[0]), "+f"(c[1]), "+f"(c[2]), "+f"(c[3])
        : "r"(a[0]), "r"(a[1]), "r"(a[2]), "r"(a[3]), "r"(b[0]), "r"(b[1]));
}
__device__ __forceinline__ void ldsm_x4(uint32_t* r, uint32_t addr) {
    asm volatile("ldmatrix.sync.aligned.m8n8.x4.shared.b16 {%0,%1,%2,%3}, [%4];"
        : "=r"(r[0]), "=r"(r[1]), "=r"(r[2]), "=r"(r[3]) : "r"(addr));
}
__device__ __forceinline__ void ldsm_x4t(uint32_t* r, uint32_t addr) {
    asm volatile("ldmatrix.sync.aligned.m8n8.x4.trans.shared.b16 {%0,%1,%2,%3}, [%4];"
        : "=r"(r[0]), "=r"(r[1]), "=r"(r[2]), "=r"(r[3]) : "r"(addr));
}
__device__ __forceinline__ void ldsm_x2(uint32_t* r, uint32_t addr) {
    asm volatile("ldmatrix.sync.aligned.m8n8.x2.shared.b16 {%0,%1}, [%2];"
        : "=r"(r[0]), "=r"(r[1]) : "r"(addr));
}
__device__ __forceinline__ void cpa16(uint32_t s, const void* g) {
    asm volatile("cp.async.cg.shared.global [%0], [%1], 16;\n" :: "r"(s), "l"(g));
}
#define CP_COMMIT() asm volatile("cp.async.commit_group;")

// ======================= weight transpose + bf16 convert ===================
__global__ void wtrans_qkv(const float* __restrict__ src) {   // [1024][3072]
    __shared__ float t[32][33];
    int c0 = blockIdx.x * 32, r0 = blockIdx.y * 32;
    int x = threadIdx.x, y = threadIdx.y;
    #pragma unroll
    for (int j = 0; j < 32; j += 8)
        t[y+j][x] = src[(size_t)(r0+y+j) * 3072 + c0 + x];
    __syncthreads();
    #pragma unroll
    for (int j = 0; j < 32; j += 8)
        g_wqT[(size_t)(c0+y+j) * 1024 + r0 + x] = __float2bfloat16(t[x][y+j]);
}
__global__ void wtrans_proj(const float* __restrict__ src) {  // [1024][1024]
    __shared__ float t[32][33];
    int c0 = blockIdx.x * 32, r0 = blockIdx.y * 32;
    int x = threadIdx.x, y = threadIdx.y;
    #pragma unroll
    for (int j = 0; j < 32; j += 8)
        t[y+j][x] = src[(size_t)(r0+y+j) * 1024 + c0 + x];
    __syncthreads();
    #pragma unroll
    for (int j = 0; j < 32; j += 8)
        g_wpT[(size_t)(c0+y+j) * 1024 + r0 + x] = __float2bfloat16(t[x][y+j]);
}

// ======================= LayerNorm (bf16 out) ==============================
__global__ void ln_kernel(const float* __restrict__ x,
                          const float* __restrict__ gamma,
                          const float* __restrict__ beta) {
    int row = blockIdx.x;
    int tid = threadIdx.x;                         // 256 threads, 4 floats each
    const float4* xr = reinterpret_cast<const float4*>(x + (size_t)row * D_);
    float4 v = xr[tid];
    float s  = v.x + v.y + v.z + v.w;
    float sq = v.x*v.x + v.y*v.y + v.z*v.z + v.w*v.w;
    #pragma unroll
    for (int o = 16; o > 0; o >>= 1) {
        s  += __shfl_xor_sync(0xffffffffu, s,  o);
        sq += __shfl_xor_sync(0xffffffffu, sq, o);
    }
    __shared__ float ss[8], sq2[8];
    __shared__ float mu_s, rs_s;
    if ((tid & 31) == 0) { ss[tid >> 5] = s; sq2[tid >> 5] = sq; }
    __syncthreads();
    if (tid == 0) {
        float a = 0.f, b2 = 0.f;
        #pragma unroll
        for (int i = 0; i < 8; i++) { a += ss[i]; b2 += sq2[i]; }
        float mu  = a * (1.0f / D_);
        float var = b2 * (1.0f / D_) - mu * mu;
        mu_s = mu;
        rs_s = rsqrtf(var + 1e-5f);
    }
    __syncthreads();
    float mu = mu_s, rs = rs_s;
    float4 g  = reinterpret_cast<const float4*>(gamma)[tid];
    float4 be = reinterpret_cast<const float4*>(beta)[tid];
    float o0 = (v.x - mu) * rs * g.x + be.x;
    float o1 = (v.y - mu) * rs * g.y + be.y;
    float o2 = (v.z - mu) * rs * g.z + be.z;
    float o3 = (v.w - mu) * rs * g.w + be.w;
    uint2 packed = make_uint2(pack_bf16(o0, o1), pack_bf16(o2, o3));
    *reinterpret_cast<uint2*>(g_xnh + (size_t)row * D_ + tid * 4) = packed;
}

// ======================= bf16 GEMM core (128x128 tile, BK=64, cp.async) ====
// A: [M][1024] bf16 row-major. B: [N][1024] bf16 (n-major, k contiguous).
// row stride 144 B (72 halves). stage stride 18432 B. A: [0,36864), B: [36864,73728).
__device__ __forceinline__ void gemm_core_bf16(
    const bf16* __restrict__ Agm, const bf16* __restrict__ Bgm,
    int m0, int n0, float acc[4][4][4])
{
    extern __shared__ uint32_t smem_u[];
    uint32_t smem_b = (uint32_t)__cvta_generic_to_shared(smem_u);
    int tid = threadIdx.x, lane = tid & 31, wid = tid >> 5;
    int warp_m = (wid & 1) * 64, warp_n = (wid >> 1) * 32;
    int lrow = tid & 127, lpart = tid >> 7;        // 0/1 -> halves of the 128B k-row

    const bf16* ag = Agm + (size_t)(m0 + lrow) * D_ + lpart * 32;
    const bf16* bg = Bgm + (size_t)(n0 + lrow) * D_ + lpart * 32;
    uint32_t sa = smem_b + lrow * 144 + lpart * 64;            // A stage0
    uint32_t sb = smem_b + 36864 + lrow * 144 + lpart * 64;    // B stage0

    #pragma unroll
    for (int j = 0; j < 4; j++) {
        cpa16(sa + j * 16, ag + j * 8);
        cpa16(sb + j * 16, bg + j * 8);
    }
    CP_COMMIT();

    uint32_t a_lane = smem_b + (warp_m + (lane & 15)) * 144 + ((lane >> 4) << 4);
    uint32_t b_lane = smem_b + 36864 + (warp_n + (lane & 7)) * 144 + (((lane >> 3) & 1) << 4);

    for (int it = 0; it < 16; it++) {
        if (it < 15) {
            int st = (it + 1) & 1;
            const bf16* agn = ag + (it + 1) * 64;
            const bf16* bgn = bg + (it + 1) * 64;
            uint32_t san = sa + st * 18432;
            uint32_t sbn = sb + st * 18432;
            #pragma unroll
            for (int j = 0; j < 4; j++) {
                cpa16(san + j * 16, agn + j * 8);
                cpa16(sbn + j * 16, bgn + j * 8);
            }
            CP_COMMIT();
            asm volatile("cp.async.wait_group 1;");
        } else {
            asm volatile("cp.async.wait_group 0;");
        }
        __syncthreads();
        uint32_t ab = a_lane + (it & 1) * 18432;
        uint32_t bb = b_lane + (it & 1) * 18432;
        #pragma unroll
        for (int c = 0; c < 4; c++) {                 // 4 chunks of k16
            uint32_t af[4][4], bfr[4][2];
            #pragma unroll
            for (int mt = 0; mt < 4; mt++) ldsm_x4(af[mt], ab + mt * 2304 + c * 32);
            #pragma unroll
            for (int nt = 0; nt < 4; nt++) ldsm_x2(bfr[nt], bb + nt * 1152 + c * 32);
            #pragma unroll
            for (int mt = 0; mt < 4; mt++)
                #pragma unroll
                for (int nt = 0; nt < 4; nt++)
                    mma_bf16(acc[mt][nt], af[mt], bfr[nt]);
        }
        __syncthreads();
    }
}

#define GEMM_SMEM 73728

// ======================= QKV GEMM ==========================================
__global__ __launch_bounds__(256, 2) void qkv_gemm(const float* __restrict__ bias) {
    float acc[4][4][4] = {};
    int m0 = blockIdx.y * 128, n0 = blockIdx.x * 128;
    gemm_core_bf16(g_xnh, g_wqT, m0, n0, acc);

    int lane = threadIdx.x & 31, wid = threadIdx.x >> 5;
    int warp_m = (wid & 1) * 64, warp_n = (wid >> 1) * 32;
    #pragma unroll
    for (int mt = 0; mt < 4; mt++) {
        #pragma unroll
        for (int half = 0; half < 2; half++) {
            int bt = m0 + warp_m + mt * 16 + (lane >> 2) + half * 8;
            int bb = bt >> 11;
            int t  = bt & 2047;
            #pragma unroll
            for (int nt = 0; nt < 4; nt++) {
                int c = n0 + warp_n + nt * 8 + (lane & 3) * 2;
                float v0 = acc[mt][nt][half*2+0] + bias[c];
                float v1 = acc[mt][nt][half*2+1] + bias[c+1];
                int s   = c >> 10;
                int rem = c & 1023;
                int hh  = rem >> 6;
                int d   = rem & 63;
                bf16* dst = (s == 0) ? g_q : ((s == 1) ? g_k : g_v);
                *reinterpret_cast<uint32_t*>(
                    &dst[((size_t)((bb * H_ + hh) * T_) + t) * HD_ + d]) =
                    pack_bf16(v0, v1);
            }
        }
    }
}

// ======================= Proj GEMM + bias + residual =======================
__global__ __launch_bounds__(256, 2) void proj_gemm(const float* __restrict__ bias,
                                                    const float* __restrict__ xres,
                                                    float* __restrict__ out) {
    float acc[4][4][4] = {};
    int m0 = blockIdx.y * 128, n0 = blockIdx.x * 128;
    gemm_core_bf16(g_aoh, g_wpT, m0, n0, acc);

    int lane = threadIdx.x & 31, wid = threadIdx.x >> 5;
    int warp_m = (wid & 1) * 64, warp_n = (wid >> 1) * 32;
    #pragma unroll
    for (int mt = 0; mt < 4; mt++) {
        #pragma unroll
        for (int half = 0; half < 2; half++) {
            int row = m0 + warp_m + mt * 16 + (lane >> 2) + half * 8;
            #pragma unroll
            for (int nt = 0; nt < 4; nt++) {
                int c = n0 + warp_n + nt * 8 + (lane & 3) * 2;
                float2 bi = *reinterpret_cast<const float2*>(&bias[c]);
                float2 xr = *reinterpret_cast<const float2*>(&xres[(size_t)row * D_ + c]);
                float2 o;
                o.x = acc[mt][nt][half*2+0] + bi.x + xr.x;
                o.y = acc[mt][nt][half*2+1] + bi.y + xr.y;
                *reinterpret_cast<float2*>(&out[(size_t)row * D_ + c]) = o;
            }
        }
    }
}

// ======================= Flash Attention v2 (register softmax) =============
// Per block: one (b, h, 128-q tile). 256 threads = 8 warps, each warp owns
// 16 q-rows x ALL keys -> softmax fully warp-local (shfl over 4-lane group).
// KV tiles of 64 keys, 32 iterations, double-buffered cp.async.
// P never touches smem: C-frag of S == A-frag of PV (pack bf16x2 in regs).
// smem: Q [0,18432) 128x144B ; K[2] [18432,36864) ; V[2] [36864,55296)
#define ATTN_SMEM 55296

__global__ __launch_bounds__(256, 2) void attn_kernel() {
    extern __shared__ char smraw[];
    uint32_t smem_b = (uint32_t)__cvta_generic_to_shared(smraw);
    const uint32_t K_BASE = 18432, V_BASE = 36864, KV_STG = 9216;

    int tid  = threadIdx.x;
    int lane = tid & 31, wid = tid >> 5;
    int warp_m = wid * 16;            // 16 q-rows per warp
    int g = lane >> 2;                // row-in-8

    int qtile = blockIdx.x, h = blockIdx.y, b = blockIdx.z;
    size_t bh = (size_t)(b * H_ + h) * T_ * HD_;
    const bf16* Qg  = g_q + bh + (size_t)qtile * 128 * HD_;
    const bf16* Kg0 = g_k + bh;
    const bf16* Vg0 = g_v + bh;

    // ---- initial loads: Q (16KB, 64B/thread), K0+V0 (8KB each, 32B/thread)
    {
        int qr = tid >> 1, qh = tid & 1;
        uint32_t dq = smem_b + qr * 144 + qh * 64;
        const bf16* sq = Qg + qr * 64 + qh * 32;
        cpa16(dq, sq); cpa16(dq + 16, sq + 8);
        cpa16(dq + 32, sq + 16); cpa16(dq + 48, sq + 24);
    }
    int kr = tid >> 2, kp = tid & 3;
    {
        uint32_t dk = smem_b + K_BASE + kr * 144 + kp * 32;
        uint32_t dv = smem_b + V_BASE + kr * 144 + kp * 32;
        const bf16* sk = Kg0 + kr * 64 + kp * 16;
        const bf16* sv = Vg0 + kr * 64 + kp * 16;
        cpa16(dk, sk); cpa16(dk + 16, sk + 8);
        cpa16(dv, sv); cpa16(dv + 16, sv + 8);
    }
    CP_COMMIT();

    // lane-invariant fragment addresses
    uint32_t q_lane = smem_b + (warp_m + (lane & 15)) * 144 + ((lane >> 4) << 4);
    // K x4: lanes 0-15 -> n-tile np*2, lanes 16-31 -> n-tile np*2+1 (+8 key rows)
    uint32_t k_lane = smem_b + K_BASE + (lane & 7) * 144 +
                      (((lane >> 3) & 1) << 4) + (lane >> 4) * 1152;
    // V x4 trans: lanes 0-15 -> d-tile 2np, lanes 16-31 -> d-tile 2np+1 (+16B)
    uint32_t v_lane = smem_b + V_BASE + (lane & 15) * 144 + (lane >> 4) * 16;

    float O[8][4] = {};               // 16 rows x 64 d per warp
    float m0r = -1e30f, m1r = -1e30f; // running max, rows g / g+8
    float l0 = 0.f, l1 = 0.f;

    for (int kt = 0; kt < 32; kt++) {
        if (kt < 31) {
            int st = (kt + 1) & 1;
            const bf16* sk = Kg0 + (size_t)(kt + 1) * 64 * HD_ + kr * 64 + kp * 16;
            const bf16* sv = Vg0 + (size_t)(kt + 1) * 64 * HD_ + kr * 64 + kp * 16;
            uint32_t dk = smem_b + K_BASE + st * KV_STG + kr * 144 + kp * 32;
            uint32_t dv = smem_b + V_BASE + st * KV_STG + kr * 144 + kp * 32;
            cpa16(dk, sk); cpa16(dk + 16, sk + 8);
            cpa16(dv, sv); cpa16(dv + 16, sv + 8);
            CP_COMMIT();
            asm volatile("cp.async.wait_group 1;");
        } else {
            asm volatile("cp.async.wait_group 0;");
        }
        __syncthreads();
        uint32_t kb = k_lane + (kt & 1) * KV_STG;
        uint32_t vb = v_lane + (kt & 1) * KV_STG;

        // ---- S = Q K^T : 16 rows x 64 keys --------------------------------
        float sacc[8][4] = {};
        #pragma unroll
        for (int c = 0; c < 4; c++) {             // k16 chunks over HD=64
            uint32_t qf[4];
            ldsm_x4(qf, q_lane + c * 32);
            #pragma unroll
            for (int np = 0; np < 4; np++) {      // pairs of key n-tiles
                uint32_t kf[4];
                ldsm_x4(kf, kb + np * 2304 + c * 32);
                mma_bf16(sacc[2*np],     qf, kf);
                mma_bf16(sacc[2*np + 1], qf, kf + 2);
            }
        }

        // ---- register softmax (rows g and g+8) ----------------------------
        const float scale = 0.125f;
        float mx0 = -1e30f, mx1 = -1e30f;
        #pragma unroll
        for (int nt = 0; nt < 8; nt++) {
            sacc[nt][0] *= scale; sacc[nt][1] *= scale;
            sacc[nt][2] *= scale; sacc[nt][3] *= scale;
            mx0 = fmaxf(mx0, fmaxf(sacc[nt][0], sacc[nt][1]));
            mx1 = fmaxf(mx1, fmaxf(sacc[nt][2], sacc[nt][3]));
        }
        mx0 = fmaxf(mx0, __shfl_xor_sync(0xffffffffu, mx0, 1));
        mx0 = fmaxf(mx0, __shfl_xor_sync(0xffffffffu, mx0, 2));
        mx1 = fmaxf(mx1, __shfl_xor_sync(0xffffffffu, mx1, 1));
        mx1 = fmaxf(mx1, __shfl_xor_sync(0xffffffffu, mx1, 2));
        float mn0 = fmaxf(m0r, mx0), mn1 = fmaxf(m1r, mx1);
        float al0 = __expf(m0r - mn0), al1 = __expf(m1r - mn1);
        float s0 = 0.f, s1 = 0.f;
        uint32_t pf[4][4];                        // P as A-frags, 4 k16 chunks
        #pragma unroll
        for (int np = 0; np < 4; np++) {
            float p00 = __expf(sacc[2*np][0]   - mn0), p01 = __expf(sacc[2*np][1]   - mn0);
            float p10 = __expf(sacc[2*np][2]   - mn1), p11 = __expf(sacc[2*np][3]   - mn1);
            float p02 = __expf(sacc[2*np+1][0] - mn0), p03 = __expf(sacc[2*np+1][1] - mn0);
            float p12 = __expf(sacc[2*np+1][2] - mn1), p13 = __expf(sacc[2*np+1][3] - mn1);
            s0 += (p00 + p01) + (p02 + p03);
            s1 += (p10 + p11) + (p12 + p13);
            pf[np][0] = pack_bf16(p00, p01);      // row g,   k 0-7  of chunk
            pf[np][1] = pack_bf16(p10, p11);      // row g+8, k 0-7
            pf[np][2] = pack_bf16(p02, p03);      // row g,   k 8-15
            pf[np][3] = pack_bf16(p12, p13);      // row g+8, k 8-15
        }
        s0 += __shfl_xor_sync(0xffffffffu, s0, 1);
        s0 += __shfl_xor_sync(0xffffffffu, s0, 2);
        s1 += __shfl_xor_sync(0xffffffffu, s1, 1);
        s1 += __shfl_xor_sync(0xffffffffu, s1, 2);
        l0 = l0 * al0 + s0;
        l1 = l1 * al1 + s1;
        m0r = mn0; m1r = mn1;

        // ---- O = O*alpha + P V -------------------------------------------
        #pragma unroll
        for (int nt = 0; nt < 8; nt++) {
            O[nt][0] *= al0; O[nt][1] *= al0;
            O[nt][2] *= al1; O[nt][3] *= al1;
        }
        #pragma unroll
        for (int kc = 0; kc < 4; kc++) {          // k16 chunks over 64 keys
            #pragma unroll
            for (int np = 0; np < 4; np++) {      // pairs of d-tiles
                uint32_t vf[4];
                ldsm_x4t(vf, vb + kc * 2304 + np * 32);
                mma_bf16(O[2*np],     pf[kc], vf);
                mma_bf16(O[2*np + 1], pf[kc], vf + 2);
            }
        }
        __syncthreads();   // all reads of buf[kt&1] done before next prefetch
    }

    // ---- epilogue: O/l -> bf16 -> g_aoh [B,T,D] ---------------------------
    float li0 = 1.f / l0, li1 = 1.f / l1;
    size_t outbase = ((size_t)b * T_ + qtile * 128 + warp_m) * D_ + h * HD_;
    int t2 = (lane & 3) * 2;
    #pragma unroll
    for (int nt = 0; nt < 8; nt++) {
        int c = nt * 8 + t2;
        *reinterpret_cast<uint32_t*>(&g_aoh[outbase + (size_t)g * D_ + c]) =
            pack_bf16(O[nt][0] * li0, O[nt][1] * li0);
        *reinterpret_cast<uint32_t*>(&g_aoh[outbase + (size_t)(g + 8) * D_ + c]) =
            pack_bf16(O[nt][2] * li1, O[nt][3] * li1);
    }
}

// ======================= launch ============================================
extern "C" void kernel_launch(void* const* d_in, const int* in_sizes, int n_in,
                              void* d_out, int out_size) {
    const float* x      = (const float*)d_in[0];
    const float* w_qkv  = (const float*)d_in[1];
    const float* b_qkv  = (const float*)d_in[2];
    const float* w_proj = (const float*)d_in[3];
    const float* b_proj = (const float*)d_in[4];
    const float* gamma  = (const float*)d_in[5];
    const float* beta   = (const float*)d_in[6];
    float* out = (float*)d_out;

    cudaFuncSetAttribute(attn_kernel,
                         cudaFuncAttributeMaxDynamicSharedMemorySize, ATTN_SMEM);
    cudaFuncSetAttribute(qkv_gemm,
                         cudaFuncAttributeMaxDynamicSharedMemorySize, GEMM_SMEM);
    cudaFuncSetAttribute(proj_gemm,
                         cudaFuncAttributeMaxDynamicSharedMemorySize, GEMM_SMEM);

    wtrans_qkv<<<dim3(96, 32), dim3(32, 8)>>>(w_qkv);
    wtrans_proj<<<dim3(32, 32), dim3(32, 8)>>>(w_proj);
    ln_kernel<<<BT_, 256>>>(x, gamma, beta);
    qkv_gemm<<<dim3(24, 64), 256, GEMM_SMEM>>>(b_qkv);
    attn_kernel<<<dim3(T_ / 128, H_, B_), 256, ATTN_SMEM>>>();
    proj_gemm<<<dim3(8, 64), 256, GEMM_SMEM>>>(b_proj, x, out);
}

// round 14
// speedup vs baseline: 5.3379x; 1.6673x over previous
#include <cuda_runtime.h>
#include <cuda_bf16.h>
#include <math.h>
#include <stdint.h>

// Problem dims
#define B_   4
#define T_   2048
#define D_   1024
#define H_   16
#define HD_  64
#define BT_  (B_*T_)          // 8192 rows

typedef __nv_bfloat16 bf16;

// ---------------- scratch (device globals: no runtime allocation) ----------
__device__ bf16 g_xnh[BT_*D_];     // layernorm output bf16   [BT, D]
__device__ bf16 g_wqT[3*D_*D_];    // w_qkv transposed bf16   [3D, D] (n-major, k contiguous)
__device__ bf16 g_wpT[D_*D_];      // w_proj transposed bf16  [D, D]
__device__ bf16 g_q [BT_*D_];      // Q bf16 [B,H,T,HD]
__device__ bf16 g_k [BT_*D_];      // K bf16 [B,H,T,HD]
__device__ bf16 g_v [BT_*D_];      // V bf16 [B,H,T,HD]
__device__ bf16 g_aoh[BT_*D_];     // attention out bf16 [B,T,D]

// ---------------- helpers ---------------------------------------------------
__device__ __forceinline__ uint32_t pack_bf16(float lo, float hi) {
    uint32_t r;
    asm("cvt.rn.bf16x2.f32 %0, %1, %2;" : "=r"(r) : "f"(hi), "f"(lo));
    return r;
}
__device__ __forceinline__ void mma_bf16(float* c, const uint32_t* a, const uint32_t* b) {
    asm volatile(
        "mma.sync.aligned.m16n8k16.row.col.f32.bf16.bf16.f32 "
        "{%0,%1,%2,%3}, {%4,%5,%6,%7}, {%8,%9}, {%0,%1,%2,%3};\n"
        : "+f"(c[0]), "+f"(c[1]), "+f"(c[2]), "+f"(c[3])
        : "r"(a[0]), "r"(a[1]), "r"(a[2]), "r"(a[3]), "r"(b[0]), "r"(b[1]));
}
__device__ __forceinline__ void ldsm_x4(uint32_t* r, uint32_t addr) {
    asm volatile("ldmatrix.sync.aligned.m8n8.x4.shared.b16 {%0,%1,%2,%3}, [%4];"
        : "=r"(r[0]), "=r"(r[1]), "=r"(r[2]), "=r"(r[3]) : "r"(addr));
}
__device__ __forceinline__ void ldsm_x4t(uint32_t* r, uint32_t addr) {
    asm volatile("ldmatrix.sync.aligned.m8n8.x4.trans.shared.b16 {%0,%1,%2,%3}, [%4];"
        : "=r"(r[0]), "=r"(r[1]), "=r"(r[2]), "=r"(r[3]) : "r"(addr));
}
__device__ __forceinline__ void cpa16(uint32_t s, const void* g) {
    asm volatile("cp.async.cg.shared.global [%0], [%1], 16;\n" :: "r"(s), "l"(g));
}
#define CP_COMMIT() asm volatile("cp.async.commit_group;")

// ======================= weight transpose + bf16 convert ===================
__global__ void wtrans_qkv(const float* __restrict__ src) {   // [1024][3072]
    __shared__ float t[32][33];
    int c0 = blockIdx.x * 32, r0 = blockIdx.y * 32;
    int x = threadIdx.x, y = threadIdx.y;
    #pragma unroll
    for (int j = 0; j < 32; j += 8)
        t[y+j][x] = src[(size_t)(r0+y+j) * 3072 + c0 + x];
    __syncthreads();
    #pragma unroll
    for (int j = 0; j < 32; j += 8)
        g_wqT[(size_t)(c0+y+j) * 1024 + r0 + x] = __float2bfloat16(t[x][y+j]);
}
__global__ void wtrans_proj(const float* __restrict__ src) {  // [1024][1024]
    __shared__ float t[32][33];
    int c0 = blockIdx.x * 32, r0 = blockIdx.y * 32;
    int x = threadIdx.x, y = threadIdx.y;
    #pragma unroll
    for (int j = 0; j < 32; j += 8)
        t[y+j][x] = src[(size_t)(r0+y+j) * 1024 + c0 + x];
    __syncthreads();
    #pragma unroll
    for (int j = 0; j < 32; j += 8)
        g_wpT[(size_t)(c0+y+j) * 1024 + r0 + x] = __float2bfloat16(t[x][y+j]);
}

// ======================= LayerNorm (bf16 out) ==============================
__global__ void ln_kernel(const float* __restrict__ x,
                          const float* __restrict__ gamma,
                          const float* __restrict__ beta) {
    int row = blockIdx.x;
    int tid = threadIdx.x;
    const float4* xr = reinterpret_cast<const float4*>(x + (size_t)row * D_);
    float4 v = xr[tid];
    float s  = v.x + v.y + v.z + v.w;
    float sq = v.x*v.x + v.y*v.y + v.z*v.z + v.w*v.w;
    #pragma unroll
    for (int o = 16; o > 0; o >>= 1) {
        s  += __shfl_xor_sync(0xffffffffu, s,  o);
        sq += __shfl_xor_sync(0xffffffffu, sq, o);
    }
    __shared__ float ss[8], sq2[8];
    __shared__ float mu_s, rs_s;
    if ((tid & 31) == 0) { ss[tid >> 5] = s; sq2[tid >> 5] = sq; }
    __syncthreads();
    if (tid == 0) {
        float a = 0.f, b2 = 0.f;
        #pragma unroll
        for (int i = 0; i < 8; i++) { a += ss[i]; b2 += sq2[i]; }
        float mu  = a * (1.0f / D_);
        float var = b2 * (1.0f / D_) - mu * mu;
        mu_s = mu;
        rs_s = rsqrtf(var + 1e-5f);
    }
    __syncthreads();
    float mu = mu_s, rs = rs_s;
    float4 g  = reinterpret_cast<const float4*>(gamma)[tid];
    float4 be = reinterpret_cast<const float4*>(beta)[tid];
    float o0 = (v.x - mu) * rs * g.x + be.x;
    float o1 = (v.y - mu) * rs * g.y + be.y;
    float o2 = (v.z - mu) * rs * g.z + be.z;
    float o3 = (v.w - mu) * rs * g.w + be.w;
    uint2 packed = make_uint2(pack_bf16(o0, o1), pack_bf16(o2, o3));
    *reinterpret_cast<uint2*>(g_xnh + (size_t)row * D_ + tid * 4) = packed;
}

// ======================= bf16 GEMM core: 4-stage ring, BK=32 ================
// A: [M][1024] bf16 row-major. B: [N][1024] bf16 (n-major, k contiguous).
// Stage = A[128 rows x 80B] + B[128 x 80B] = 20480 B; 4 stages = 81920 B.
// Row stride 80 B: 16B-aligned, ldsm banks (r*20)%32 distinct over 8-row phase.
// One __syncthreads per iteration; data committed 3 iterations ahead.
#define GEMM_SMEM 81920

__device__ __forceinline__ void gemm_core_bk32(
    const bf16* __restrict__ Agm, const bf16* __restrict__ Bgm,
    int m0, int n0, float acc[4][4][4])
{
    extern __shared__ uint32_t smem_u[];
    uint32_t smb = (uint32_t)__cvta_generic_to_shared(smem_u);
    int tid = threadIdx.x, lane = tid & 31, wid = tid >> 5;
    int warp_m = (wid & 1) * 64, warp_n = (wid >> 1) * 32;

    int row = tid & 127, mat = tid >> 7;           // 0 = A row, 1 = B row
    const bf16* gp = mat ? (Bgm + (size_t)(n0 + row) * D_)
                         : (Agm + (size_t)(m0 + row) * D_);
    uint32_t sbase = smb + mat * 10240 + row * 80;

    // preload stages 0..2 (k-blocks 0..2)
    #pragma unroll
    for (int s = 0; s < 3; s++) {
        #pragma unroll
        for (int j = 0; j < 4; j++)
            cpa16(sbase + s * 20480 + j * 16, gp + s * 32 + j * 8);
        CP_COMMIT();
    }

    uint32_t a_lane = smb + (warp_m + (lane & 15)) * 80 + ((lane >> 4) << 4);
    uint32_t b_lane = smb + 10240 + (warp_n + (lane & 7)) * 80 +
                      (((lane >> 3) & 1) << 4) + (lane >> 4) * 640;

    #pragma unroll 4
    for (int it = 0; it < 32; it++) {
        if (it < 30)       asm volatile("cp.async.wait_group 2;");
        else if (it == 30) asm volatile("cp.async.wait_group 1;");
        else               asm volatile("cp.async.wait_group 0;");
        __syncthreads();   // stage it%4 visible; stage (it+3)%4 consumers (it-1) done

        if (it < 29) {     // prefetch k-block it+3 into ring slot (it+3)%4
            uint32_t d2 = sbase + ((it + 3) & 3) * 20480;
            const bf16* g2 = gp + (it + 3) * 32;
            #pragma unroll
            for (int j = 0; j < 4; j++)
                cpa16(d2 + j * 16, g2 + j * 8);
            CP_COMMIT();
        }

        uint32_t ab = a_lane + (it & 3) * 20480;
        uint32_t bb = b_lane + (it & 3) * 20480;
        #pragma unroll
        for (int c = 0; c < 2; c++) {              // 2 chunks of k16
            uint32_t af[4][4], bfr[2][4];
            #pragma unroll
            for (int mt = 0; mt < 4; mt++) ldsm_x4(af[mt], ab + mt * 1280 + c * 32);
            #pragma unroll
            for (int np = 0; np < 2; np++) ldsm_x4(bfr[np], bb + np * 1280 + c * 32);
            #pragma unroll
            for (int mt = 0; mt < 4; mt++)
                #pragma unroll
                for (int np = 0; np < 2; np++) {
                    mma_bf16(acc[mt][2*np],     af[mt], bfr[np]);
                    mma_bf16(acc[mt][2*np + 1], af[mt], bfr[np] + 2);
                }
        }
    }
    __syncthreads();
}

// ======================= QKV GEMM ==========================================
__global__ __launch_bounds__(256, 2) void qkv_gemm(const float* __restrict__ bias) {
    float acc[4][4][4] = {};
    int m0 = blockIdx.y * 128, n0 = blockIdx.x * 128;
    gemm_core_bk32(g_xnh, g_wqT, m0, n0, acc);

    int lane = threadIdx.x & 31, wid = threadIdx.x >> 5;
    int warp_m = (wid & 1) * 64, warp_n = (wid >> 1) * 32;
    #pragma unroll
    for (int mt = 0; mt < 4; mt++) {
        #pragma unroll
        for (int half = 0; half < 2; half++) {
            int bt = m0 + warp_m + mt * 16 + (lane >> 2) + half * 8;
            int bb = bt >> 11;
            int t  = bt & 2047;
            #pragma unroll
            for (int nt = 0; nt < 4; nt++) {
                int c = n0 + warp_n + nt * 8 + (lane & 3) * 2;
                float v0 = acc[mt][nt][half*2+0] + bias[c];
                float v1 = acc[mt][nt][half*2+1] + bias[c+1];
                int s   = c >> 10;
                int rem = c & 1023;
                int hh  = rem >> 6;
                int d   = rem & 63;
                bf16* dst = (s == 0) ? g_q : ((s == 1) ? g_k : g_v);
                *reinterpret_cast<uint32_t*>(
                    &dst[((size_t)((bb * H_ + hh) * T_) + t) * HD_ + d]) =
                    pack_bf16(v0, v1);
            }
        }
    }
}

// ======================= Proj GEMM + bias + residual =======================
__global__ __launch_bounds__(256, 2) void proj_gemm(const float* __restrict__ bias,
                                                    const float* __restrict__ xres,
                                                    float* __restrict__ out) {
    float acc[4][4][4] = {};
    int m0 = blockIdx.y * 128, n0 = blockIdx.x * 128;
    gemm_core_bk32(g_aoh, g_wpT, m0, n0, acc);

    int lane = threadIdx.x & 31, wid = threadIdx.x >> 5;
    int warp_m = (wid & 1) * 64, warp_n = (wid >> 1) * 32;
    #pragma unroll
    for (int mt = 0; mt < 4; mt++) {
        #pragma unroll
        for (int half = 0; half < 2; half++) {
            int row = m0 + warp_m + mt * 16 + (lane >> 2) + half * 8;
            #pragma unroll
            for (int nt = 0; nt < 4; nt++) {
                int c = n0 + warp_n + nt * 8 + (lane & 3) * 2;
                float2 bi = *reinterpret_cast<const float2*>(&bias[c]);
                float2 xr = *reinterpret_cast<const float2*>(&xres[(size_t)row * D_ + c]);
                float2 o;
                o.x = acc[mt][nt][half*2+0] + bi.x + xr.x;
                o.y = acc[mt][nt][half*2+1] + bi.y + xr.y;
                *reinterpret_cast<float2*>(&out[(size_t)row * D_ + c]) = o;
            }
        }
    }
}

// ======================= Flash Attention v2 (register softmax) =============
// (unchanged from R10 — passing at rel_err 4.2e-5)
#define ATTN_SMEM 55296

__global__ __launch_bounds__(256, 2) void attn_kernel() {
    extern __shared__ char smraw[];
    uint32_t smem_b = (uint32_t)__cvta_generic_to_shared(smraw);
    const uint32_t K_BASE = 18432, V_BASE = 36864, KV_STG = 9216;

    int tid  = threadIdx.x;
    int lane = tid & 31, wid = tid >> 5;
    int warp_m = wid * 16;
    int g = lane >> 2;

    int qtile = blockIdx.x, h = blockIdx.y, b = blockIdx.z;
    size_t bh = (size_t)(b * H_ + h) * T_ * HD_;
    const bf16* Qg  = g_q + bh + (size_t)qtile * 128 * HD_;
    const bf16* Kg0 = g_k + bh;
    const bf16* Vg0 = g_v + bh;

    {
        int qr = tid >> 1, qh = tid & 1;
        uint32_t dq = smem_b + qr * 144 + qh * 64;
        const bf16* sq = Qg + qr * 64 + qh * 32;
        cpa16(dq, sq); cpa16(dq + 16, sq + 8);
        cpa16(dq + 32, sq + 16); cpa16(dq + 48, sq + 24);
    }
    int kr = tid >> 2, kp = tid & 3;
    {
        uint32_t dk = smem_b + K_BASE + kr * 144 + kp * 32;
        uint32_t dv = smem_b + V_BASE + kr * 144 + kp * 32;
        const bf16* sk = Kg0 + kr * 64 + kp * 16;
        const bf16* sv = Vg0 + kr * 64 + kp * 16;
        cpa16(dk, sk); cpa16(dk + 16, sk + 8);
        cpa16(dv, sv); cpa16(dv + 16, sv + 8);
    }
    CP_COMMIT();

    uint32_t q_lane = smem_b + (warp_m + (lane & 15)) * 144 + ((lane >> 4) << 4);
    uint32_t k_lane = smem_b + K_BASE + (lane & 7) * 144 +
                      (((lane >> 3) & 1) << 4) + (lane >> 4) * 1152;
    uint32_t v_lane = smem_b + V_BASE + (lane & 15) * 144 + (lane >> 4) * 16;

    float O[8][4] = {};
    float m0r = -1e30f, m1r = -1e30f;
    float l0 = 0.f, l1 = 0.f;

    for (int kt = 0; kt < 32; kt++) {
        if (kt < 31) {
            int st = (kt + 1) & 1;
            const bf16* sk = Kg0 + (size_t)(kt + 1) * 64 * HD_ + kr * 64 + kp * 16;
            const bf16* sv = Vg0 + (size_t)(kt + 1) * 64 * HD_ + kr * 64 + kp * 16;
            uint32_t dk = smem_b + K_BASE + st * KV_STG + kr * 144 + kp * 32;
            uint32_t dv = smem_b + V_BASE + st * KV_STG + kr * 144 + kp * 32;
            cpa16(dk, sk); cpa16(dk + 16, sk + 8);
            cpa16(dv, sv); cpa16(dv + 16, sv + 8);
            CP_COMMIT();
            asm volatile("cp.async.wait_group 1;");
        } else {
            asm volatile("cp.async.wait_group 0;");
        }
        __syncthreads();
        uint32_t kb = k_lane + (kt & 1) * KV_STG;
        uint32_t vb = v_lane + (kt & 1) * KV_STG;

        float sacc[8][4] = {};
        #pragma unroll
        for (int c = 0; c < 4; c++) {
            uint32_t qf[4];
            ldsm_x4(qf, q_lane + c * 32);
            #pragma unroll
            for (int np = 0; np < 4; np++) {
                uint32_t kf[4];
                ldsm_x4(kf, kb + np * 2304 + c * 32);
                mma_bf16(sacc[2*np],     qf, kf);
                mma_bf16(sacc[2*np + 1], qf, kf + 2);
            }
        }

        const float scale = 0.125f;
        float mx0 = -1e30f, mx1 = -1e30f;
        #pragma unroll
        for (int nt = 0; nt < 8; nt++) {
            sacc[nt][0] *= scale; sacc[nt][1] *= scale;
            sacc[nt][2] *= scale; sacc[nt][3] *= scale;
            mx0 = fmaxf(mx0, fmaxf(sacc[nt][0], sacc[nt][1]));
            mx1 = fmaxf(mx1, fmaxf(sacc[nt][2], sacc[nt][3]));
        }
        mx0 = fmaxf(mx0, __shfl_xor_sync(0xffffffffu, mx0, 1));
        mx0 = fmaxf(mx0, __shfl_xor_sync(0xffffffffu, mx0, 2));
        mx1 = fmaxf(mx1, __shfl_xor_sync(0xffffffffu, mx1, 1));
        mx1 = fmaxf(mx1, __shfl_xor_sync(0xffffffffu, mx1, 2));
        float mn0 = fmaxf(m0r, mx0), mn1 = fmaxf(m1r, mx1);
        float al0 = __expf(m0r - mn0), al1 = __expf(m1r - mn1);
        float s0 = 0.f, s1 = 0.f;
        uint32_t pf[4][4];
        #pragma unroll
        for (int np = 0; np < 4; np++) {
            float p00 = __expf(sacc[2*np][0]   - mn0), p01 = __expf(sacc[2*np][1]   - mn0);
            float p10 = __expf(sacc[2*np][2]   - mn1), p11 = __expf(sacc[2*np][3]   - mn1);
            float p02 = __expf(sacc[2*np+1][0] - mn0), p03 = __expf(sacc[2*np+1][1] - mn0);
            float p12 = __expf(sacc[2*np+1][2] - mn1), p13 = __expf(sacc[2*np+1][3] - mn1);
            s0 += (p00 + p01) + (p02 + p03);
            s1 += (p10 + p11) + (p12 + p13);
            pf[np][0] = pack_bf16(p00, p01);
            pf[np][1] = pack_bf16(p10, p11);
            pf[np][2] = pack_bf16(p02, p03);
            pf[np][3] = pack_bf16(p12, p13);
        }
        s0 += __shfl_xor_sync(0xffffffffu, s0, 1);
        s0 += __shfl_xor_sync(0xffffffffu, s0, 2);
        s1 += __shfl_xor_sync(0xffffffffu, s1, 1);
        s1 += __shfl_xor_sync(0xffffffffu, s1, 2);
        l0 = l0 * al0 + s0;
        l1 = l1 * al1 + s1;
        m0r = mn0; m1r = mn1;

        #pragma unroll
        for (int nt = 0; nt < 8; nt++) {
            O[nt][0] *= al0; O[nt][1] *= al0;
            O[nt][2] *= al1; O[nt][3] *= al1;
        }
        #pragma unroll
        for (int kc = 0; kc < 4; kc++) {
            #pragma unroll
            for (int np = 0; np < 4; np++) {
                uint32_t vf[4];
                ldsm_x4t(vf, vb + kc * 2304 + np * 32);
                mma_bf16(O[2*np],     pf[kc], vf);
                mma_bf16(O[2*np + 1], pf[kc], vf + 2);
            }
        }
        __syncthreads();
    }

    float li0 = 1.f / l0, li1 = 1.f / l1;
    size_t outbase = ((size_t)b * T_ + qtile * 128 + warp_m) * D_ + h * HD_;
    int t2 = (lane & 3) * 2;
    #pragma unroll
    for (int nt = 0; nt < 8; nt++) {
        int c = nt * 8 + t2;
        *reinterpret_cast<uint32_t*>(&g_aoh[outbase + (size_t)g * D_ + c]) =
            pack_bf16(O[nt][0] * li0, O[nt][1] * li0);
        *reinterpret_cast<uint32_t*>(&g_aoh[outbase + (size_t)(g + 8) * D_ + c]) =
            pack_bf16(O[nt][2] * li1, O[nt][3] * li1);
    }
}

// ======================= launch ============================================
extern "C" void kernel_launch(void* const* d_in, const int* in_sizes, int n_in,
                              void* d_out, int out_size) {
    const float* x      = (const float*)d_in[0];
    const float* w_qkv  = (const float*)d_in[1];
    const float* b_qkv  = (const float*)d_in[2];
    const float* w_proj = (const float*)d_in[3];
    const float* b_proj = (const float*)d_in[4];
    const float* gamma  = (const float*)d_in[5];
    const float* beta   = (const float*)d_in[6];
    float* out = (float*)d_out;

    cudaFuncSetAttribute(attn_kernel,
                         cudaFuncAttributeMaxDynamicSharedMemorySize, ATTN_SMEM);
    cudaFuncSetAttribute(qkv_gemm,
                         cudaFuncAttributeMaxDynamicSharedMemorySize, GEMM_SMEM);
    cudaFuncSetAttribute(proj_gemm,
                         cudaFuncAttributeMaxDynamicSharedMemorySize, GEMM_SMEM);

    wtrans_qkv<<<dim3(96, 32), dim3(32, 8)>>>(w_qkv);
    wtrans_proj<<<dim3(32, 32), dim3(32, 8)>>>(w_proj);
    ln_kernel<<<BT_, 256>>>(x, gamma, beta);
    qkv_gemm<<<dim3(24, 64), 256, GEMM_SMEM>>>(b_qkv);
    attn_kernel<<<dim3(T_ / 128, H_, B_), 256, ATTN_SMEM>>>();
    proj_gemm<<<dim3(8, 64), 256, GEMM_SMEM>>>(b_proj, x, out);
}